// round 13
// baseline (speedup 1.0000x reference)
#include <cuda_runtime.h>
#include <cuda_bf16.h>
#include <mma.h>
#include <cstdint>

using namespace nvcuda;

// ---------------- geometry ----------------
#define GD0 27
#define GH0 127
#define GW0 127
#define NVOX (GD0*GH0*GW0)        // 435483
#define GD1 14
#define GH1 64
#define GW1 64
#define NC1 (GD1*GH1*GW1)         // 57344
#define GD2 7
#define GH2 32
#define GW2 32
#define NC2 (GD2*GH2*GW2)         // 7168
#define FS 64
#define CS 96

// ---------------- static scratch (zero-init; inactive voxels never written) ----
__device__ float g_fineA[(size_t)NVOX * 4];               // scatter input (3ch used)
__device__ float g_cA[NC1 * CS];
__device__ float g_c2[NC2 * CS];
__device__ float g_mask[NC1];
__device__ float g_wi0[27 * 32 * 64];
// INTERLEAVED bf16 hi/lo activation buffers: per voxel [hi(FS) | lo(FS)]
__device__ __align__(256) __nv_bfloat16 g_fX[(size_t)NVOX * FS * 2];
__device__ __align__(256) __nv_bfloat16 g_fY[(size_t)NVOX * FS * 2];
__device__ __align__(256) __nv_bfloat16 g_cX[NC1 * CS * 2];
__device__ __align__(256) __nv_bfloat16 g_cY[NC1 * CS * 2];
// bf16 hi/lo weight images, ORIGINAL [tap][ci][co] layout
__device__ __align__(256) __nv_bfloat16 g_b1h[27 * 32 * 32],  g_b1l[27 * 32 * 32];
__device__ __align__(256) __nv_bfloat16 g_b2h[27 * 32 * 64],  g_b2l[27 * 32 * 64];
__device__ __align__(256) __nv_bfloat16 g_b3h[27 * 64 * 64],  g_b3l[27 * 64 * 64];
__device__ __align__(256) __nv_bfloat16 g_bd0h[27 * 64 * 64], g_bd0l[27 * 64 * 64];
__device__ __align__(256) __nv_bfloat16 g_b4h[27 * 64 * 96],  g_b4l[27 * 64 * 96];
__device__ __align__(256) __nv_bfloat16 g_b5h[27 * 96 * 96],  g_b5l[27 * 96 * 96];

// ---------------- helpers ----------------
__device__ __forceinline__ void packpair(float x, float y, uint32_t& h, uint32_t& l) {
    __nv_bfloat16 hx = __float2bfloat16(x), hy = __float2bfloat16(y);
    __nv_bfloat16 lx = __float2bfloat16(x - __bfloat162float(hx));
    __nv_bfloat16 ly = __float2bfloat16(y - __bfloat162float(hy));
    __nv_bfloat162 hh; hh.x = hx; hh.y = hy;
    __nv_bfloat162 ll; ll.x = lx; ll.y = ly;
    h = *reinterpret_cast<uint32_t*>(&hh);
    l = *reinterpret_cast<uint32_t*>(&ll);
}

__global__ void bprep_kernel(const float* __restrict__ W, __nv_bfloat16* __restrict__ hi,
                             __nv_bfloat16* __restrict__ lo, int tot) {
    int i = blockIdx.x * blockDim.x + threadIdx.x;
    if (i >= tot) return;
    float v = W[i];
    __nv_bfloat16 h = __float2bfloat16(v);
    hi[i] = h;
    lo[i] = __float2bfloat16(v - __bfloat162float(h));
}

__global__ void repack_kernel(const float* __restrict__ w, float* __restrict__ o,
                              int k3, int cin, int cout) {
    int i = blockIdx.x * blockDim.x + threadIdx.x;
    int tot = k3 * cin * cout;
    if (i >= tot) return;
    int co = i % cout;
    int r  = i / cout;
    int ci = r % cin;
    int t  = r / cin;
    o[(t * cout + co) * cin + ci] = w[i];
}

__global__ void scatter_kernel(const float* __restrict__ f, const int* __restrict__ coors,
                               float* __restrict__ X, int n) {
    int p = blockIdx.x * blockDim.x + threadIdx.x;
    if (p >= n) return;
    int z = coors[p * 4 + 1], y = coors[p * 4 + 2], x = coors[p * 4 + 3];
    size_t vox = (size_t)((z * GH0 + y) * GW0 + x) * 4;
    X[vox + 0] = f[p * 3 + 0];
    X[vox + 1] = f[p * 3 + 1];
    X[vox + 2] = f[p * 3 + 2];
}

__global__ void mask_kernel(const int* __restrict__ coors, float* __restrict__ mask, int n) {
    int p = blockIdx.x * blockDim.x + threadIdx.x;
    if (p >= n) return;
    int z = coors[p * 4 + 1], y = coors[p * 4 + 2], x = coors[p * 4 + 3];
    int zo[2], yo[2], xo[2];
    int nzc = 0, nyc = 0, nxc = 0;
    if ((z & 1) == 0) { zo[nzc++] = z >> 1; }
    else { zo[nzc++] = z >> 1; if ((z >> 1) + 1 < GD1) zo[nzc++] = (z >> 1) + 1; }
    if ((y & 1) == 0) { yo[nyc++] = y >> 1; }
    else { yo[nyc++] = y >> 1; if ((y >> 1) + 1 < GH1) yo[nyc++] = (y >> 1) + 1; }
    if ((x & 1) == 0) { xo[nxc++] = x >> 1; }
    else { xo[nxc++] = x >> 1; if ((x >> 1) + 1 < GW1) xo[nxc++] = (x >> 1) + 1; }
    for (int a = 0; a < nzc; a++)
        for (int b = 0; b < nyc; b++)
            for (int c = 0; c < nxc; c++)
                mask[(zo[a] * GH1 + yo[b]) * GW1 + xo[c]] = 1.0f;
}

// ---------------- sub0: 3->32, 8 points per block (one warp per point); interleaved out
__global__ void __launch_bounds__(256) conv_sub0_kernel(
    const float* __restrict__ X, __nv_bfloat16* __restrict__ Y,
    const int* __restrict__ coors, const float* __restrict__ W, int n) {
    __shared__ float xs[8][84];
    int g = threadIdx.x >> 5, t = threadIdx.x & 31;
    int p = blockIdx.x * 8 + g;
    if (p >= n) return;
    int z = coors[p * 4 + 1], y = coors[p * 4 + 2], x = coors[p * 4 + 3];
    for (int i = t; i < 81; i += 32) {
        int tap = i / 3, ci = i % 3;
        int nz = z + tap / 9 - 1;
        int ny = y + (tap / 3) % 3 - 1;
        int nx = x + tap % 3 - 1;
        bool ok = (unsigned)nz < (unsigned)GD0 && (unsigned)ny < (unsigned)GH0 &&
                  (unsigned)nx < (unsigned)GW0;
        xs[g][i] = ok ? X[(size_t)((nz * GH0 + ny) * GW0 + nx) * 4 + ci] : 0.0f;
    }
    __syncwarp();
    float a = 0.f;
#pragma unroll
    for (int i = 0; i < 81; i++) a = fmaf(W[i * 32 + t], xs[g][i], a);
    size_t v = (size_t)((z * GH0 + y) * GW0 + x) * (2 * FS);
    __nv_bfloat16 h = __float2bfloat16(a);
    Y[v + t] = h;
    Y[v + FS + t] = __float2bfloat16(a - __bfloat162float(h));
}

// ---------------- fine submanifold conv via wmma, interleaved hi/lo activations
template <int CIN, int COUT, int MTILE>
__global__ void __launch_bounds__(MTILE * 2) conv_fine_wmma(
    const __nv_bfloat16* __restrict__ X, __nv_bfloat16* __restrict__ Y,
    const int* __restrict__ coors,
    const __nv_bfloat16* __restrict__ Bhi, const __nv_bfloat16* __restrict__ Blo, int n) {
    constexpr int THREADS = MTILE * 2;
    constexpr int LDA = CIN + 8;
    constexpr int LDB = COUT + 8;
    constexpr int KGA = CIN / 8;
    constexpr int NGB = COUT / 8;
    constexpr int BGN = CIN * NGB;
    constexpr int NT = COUT / 16;
    __shared__ int s_z[MTILE], s_y[MTILE], s_x[MTILE];
    extern __shared__ __align__(256) char smem[];
    __nv_bfloat16* sAh = reinterpret_cast<__nv_bfloat16*>(smem);
    __nv_bfloat16* sAl = sAh + MTILE * LDA;
    __nv_bfloat16* sBh = sAl + MTILE * LDA;
    __nv_bfloat16* sBl = sBh + CIN * LDB;
    float* sOut = reinterpret_cast<float*>(smem);

    int tid = threadIdx.x, wid = tid >> 5;
    int p0 = blockIdx.x * MTILE;
    for (int i = tid; i < MTILE; i += THREADS) {
        int p = p0 + i;
        int zz = -8, yy = 0, xv = 0;
        if (p < n) { zz = coors[p * 4 + 1]; yy = coors[p * 4 + 2]; xv = coors[p * 4 + 3]; }
        s_z[i] = zz; s_y[i] = yy; s_x[i] = xv;
    }

    wmma::fragment<wmma::accumulator, 16, 16, 16, float> acc[NT];
#pragma unroll
    for (int i = 0; i < NT; i++) wmma::fill_fragment(acc[i], 0.0f);

    for (int tap = 0; tap < 27; tap++) {
        int dz = tap / 9 - 1, dy = (tap / 3) % 3 - 1, dx = tap % 3 - 1;
        __syncthreads();
        for (int j = tid; j < BGN; j += THREADS) {
            int ci = j / NGB, g = j - ci * NGB;
            const uint4* sh = reinterpret_cast<const uint4*>(
                Bhi + (size_t)tap * CIN * COUT + ci * COUT + g * 8);
            const uint4* sl = reinterpret_cast<const uint4*>(
                Blo + (size_t)tap * CIN * COUT + ci * COUT + g * 8);
            *reinterpret_cast<uint4*>(sBh + ci * LDB + g * 8) = *sh;
            *reinterpret_cast<uint4*>(sBl + ci * LDB + g * 8) = *sl;
        }
        for (int i = tid; i < MTILE * KGA; i += THREADS) {
            int r = i / KGA, g = i - r * KGA;
            int k = g * 8;
            int nz = s_z[r] + dz, ny = s_y[r] + dy, nx = s_x[r] + dx;
            bool ok = (unsigned)nz < (unsigned)GD0 && (unsigned)ny < (unsigned)GH0 &&
                      (unsigned)nx < (unsigned)GW0;
            uint4 vh = make_uint4(0u, 0u, 0u, 0u), vl = vh;
            if (ok) {
                size_t base = (size_t)((nz * GH0 + ny) * GW0 + nx) * (2 * FS) + k;
                vh = *reinterpret_cast<const uint4*>(X + base);
                vl = *reinterpret_cast<const uint4*>(X + base + FS);
            }
            *reinterpret_cast<uint4*>(sAh + r * LDA + k) = vh;
            *reinterpret_cast<uint4*>(sAl + r * LDA + k) = vl;
        }
        __syncthreads();
        const __nv_bfloat16* ah = sAh + wid * 16 * LDA;
        const __nv_bfloat16* al = sAl + wid * 16 * LDA;
#pragma unroll
        for (int kt = 0; kt < CIN / 16; kt++) {
            wmma::fragment<wmma::matrix_a, 16, 16, 16, __nv_bfloat16, wmma::row_major> fah, fal;
            wmma::load_matrix_sync(fah, ah + kt * 16, LDA);
            wmma::load_matrix_sync(fal, al + kt * 16, LDA);
#pragma unroll
            for (int nt = 0; nt < NT; nt++) {
                wmma::fragment<wmma::matrix_b, 16, 16, 16, __nv_bfloat16, wmma::row_major> fbh, fbl;
                wmma::load_matrix_sync(fbh, sBh + kt * 16 * LDB + nt * 16, LDB);
                wmma::load_matrix_sync(fbl, sBl + kt * 16 * LDB + nt * 16, LDB);
                wmma::mma_sync(acc[nt], fah, fbh, acc[nt]);
                wmma::mma_sync(acc[nt], fah, fbl, acc[nt]);
                wmma::mma_sync(acc[nt], fal, fbh, acc[nt]);
            }
        }
    }
    __syncthreads();
#pragma unroll
    for (int nt = 0; nt < NT; nt++)
        wmma::store_matrix_sync(sOut + wid * 16 * COUT + nt * 16, acc[nt], COUT,
                                wmma::mem_row_major);
    __syncthreads();
    for (int i = tid; i < MTILE * NGB; i += THREADS) {
        int r = i / NGB, g = i - r * NGB;
        int k = g * 8;
        int p = p0 + r;
        if (p >= n) continue;
        const float* s = sOut + r * COUT + k;
        float4 a = *reinterpret_cast<const float4*>(s);
        float4 b = *reinterpret_cast<const float4*>(s + 4);
        uint32_t h0, h1, h2, h3, l0, l1, l2, l3;
        packpair(a.x, a.y, h0, l0); packpair(a.z, a.w, h1, l1);
        packpair(b.x, b.y, h2, l2); packpair(b.z, b.w, h3, l3);
        size_t base = (size_t)((s_z[r] * GH0 + s_y[r]) * GW0 + s_x[r]) * (2 * FS) + k;
        *reinterpret_cast<uint4*>(Y + base) = make_uint4(h0, h1, h2, h3);
        *reinterpret_cast<uint4*>(Y + base + FS) = make_uint4(l0, l1, l2, l3);
    }
}

// ---------------- down0 via wmma: fine interleaved -> coarse interleaved (dense)
__global__ void __launch_bounds__(256) conv_down0_wmma(
    const __nv_bfloat16* __restrict__ X, __nv_bfloat16* __restrict__ Y,
    const __nv_bfloat16* __restrict__ Bhi, const __nv_bfloat16* __restrict__ Blo) {
    constexpr int CIN = 64, COUT = 64;
    constexpr int LDA = CIN + 8;
    constexpr int LDB = COUT + 8;
    constexpr int KGA = CIN / 8;
    constexpr int NGB = COUT / 8;
    constexpr int BGN = CIN * NGB;
    constexpr int NT = COUT / 16;
    extern __shared__ __align__(256) char smem[];
    __nv_bfloat16* sAh = reinterpret_cast<__nv_bfloat16*>(smem);
    __nv_bfloat16* sAl = sAh + 128 * LDA;
    __nv_bfloat16* sBh = sAl + 128 * LDA;
    __nv_bfloat16* sBl = sBh + CIN * LDB;
    float* sOut = reinterpret_cast<float*>(smem);

    int tid = threadIdx.x, wid = tid >> 5;
    int o0 = blockIdx.x * 128;

    wmma::fragment<wmma::accumulator, 16, 16, 16, float> acc[NT];
#pragma unroll
    for (int i = 0; i < NT; i++) wmma::fill_fragment(acc[i], 0.0f);

    for (int tap = 0; tap < 27; tap++) {
        int dz = tap / 9 - 1, dy = (tap / 3) % 3 - 1, dx = tap % 3 - 1;
        __syncthreads();
        for (int j = tid; j < BGN; j += 256) {
            int ci = j / NGB, g = j - ci * NGB;
            const uint4* sh = reinterpret_cast<const uint4*>(
                Bhi + (size_t)tap * CIN * COUT + ci * COUT + g * 8);
            const uint4* sl = reinterpret_cast<const uint4*>(
                Blo + (size_t)tap * CIN * COUT + ci * COUT + g * 8);
            *reinterpret_cast<uint4*>(sBh + ci * LDB + g * 8) = *sh;
            *reinterpret_cast<uint4*>(sBl + ci * LDB + g * 8) = *sl;
        }
        for (int i = tid; i < 128 * KGA; i += 256) {
            int r = i / KGA, g = i - r * KGA;
            int k = g * 8;
            int o = o0 + r;
            int oz = o >> 12, oy = (o >> 6) & 63, ox = o & 63;
            int nz = 2 * oz + dz, ny = 2 * oy + dy, nx = 2 * ox + dx;
            bool ok = (unsigned)nz < (unsigned)GD0 && (unsigned)ny < (unsigned)GH0 &&
                      (unsigned)nx < (unsigned)GW0;
            uint4 vh = make_uint4(0u, 0u, 0u, 0u), vl = vh;
            if (ok) {
                size_t base = (size_t)((nz * GH0 + ny) * GW0 + nx) * (2 * FS) + k;
                vh = *reinterpret_cast<const uint4*>(X + base);
                vl = *reinterpret_cast<const uint4*>(X + base + FS);
            }
            *reinterpret_cast<uint4*>(sAh + r * LDA + k) = vh;
            *reinterpret_cast<uint4*>(sAl + r * LDA + k) = vl;
        }
        __syncthreads();
        const __nv_bfloat16* ah = sAh + wid * 16 * LDA;
        const __nv_bfloat16* al = sAl + wid * 16 * LDA;
#pragma unroll
        for (int kt = 0; kt < CIN / 16; kt++) {
            wmma::fragment<wmma::matrix_a, 16, 16, 16, __nv_bfloat16, wmma::row_major> fah, fal;
            wmma::load_matrix_sync(fah, ah + kt * 16, LDA);
            wmma::load_matrix_sync(fal, al + kt * 16, LDA);
#pragma unroll
            for (int nt = 0; nt < NT; nt++) {
                wmma::fragment<wmma::matrix_b, 16, 16, 16, __nv_bfloat16, wmma::row_major> fbh, fbl;
                wmma::load_matrix_sync(fbh, sBh + kt * 16 * LDB + nt * 16, LDB);
                wmma::load_matrix_sync(fbl, sBl + kt * 16 * LDB + nt * 16, LDB);
                wmma::mma_sync(acc[nt], fah, fbh, acc[nt]);
                wmma::mma_sync(acc[nt], fah, fbl, acc[nt]);
                wmma::mma_sync(acc[nt], fal, fbh, acc[nt]);
            }
        }
    }
    __syncthreads();
#pragma unroll
    for (int nt = 0; nt < NT; nt++)
        wmma::store_matrix_sync(sOut + wid * 16 * COUT + nt * 16, acc[nt], COUT,
                                wmma::mem_row_major);
    __syncthreads();
    for (int i = tid; i < 128 * NGB; i += 256) {
        int r = i / NGB, g = i - r * NGB;
        int k = g * 8;
        const float* s = sOut + r * COUT + k;
        float4 a = *reinterpret_cast<const float4*>(s);
        float4 b = *reinterpret_cast<const float4*>(s + 4);
        uint32_t h0, h1, h2, h3, l0, l1, l2, l3;
        packpair(a.x, a.y, h0, l0); packpair(a.z, a.w, h1, l1);
        packpair(b.x, b.y, h2, l2); packpair(b.z, b.w, h3, l3);
        size_t base = (size_t)(o0 + r) * (2 * CS) + k;
        *reinterpret_cast<uint4*>(Y + base) = make_uint4(h0, h1, h2, h3);
        *reinterpret_cast<uint4*>(Y + base + CS) = make_uint4(l0, l1, l2, l3);
    }
}

// ---------------- wmma coarse conv (k=3,s=1,p=1), masked, interleaved input
template <int CIN, bool OUT16>
__global__ void __launch_bounds__(256) conv_coarse_wmma(
    const __nv_bfloat16* __restrict__ X,
    float* __restrict__ Yf, __nv_bfloat16* __restrict__ Y16,
    const __nv_bfloat16* __restrict__ Bhi, const __nv_bfloat16* __restrict__ Blo,
    const float* __restrict__ mask) {
    constexpr int COUT = 96;
    constexpr int LDA = CIN + 8;
    constexpr int LDB = COUT + 8;
    constexpr int KGA = CIN / 8;
    constexpr int NGB = COUT / 8;
    constexpr int BGN = CIN * NGB;
    extern __shared__ __align__(256) char smem[];
    __nv_bfloat16* sAh = reinterpret_cast<__nv_bfloat16*>(smem);
    __nv_bfloat16* sAl = sAh + 128 * LDA;
    __nv_bfloat16* sBh = sAl + 128 * LDA;
    __nv_bfloat16* sBl = sBh + CIN * LDB;
    float* sOut = reinterpret_cast<float*>(smem);

    int tid = threadIdx.x, wid = tid >> 5;
    int o0 = blockIdx.x * 128;

    wmma::fragment<wmma::accumulator, 16, 16, 16, float> acc[6];
#pragma unroll
    for (int i = 0; i < 6; i++) wmma::fill_fragment(acc[i], 0.0f);

    for (int tap = 0; tap < 27; tap++) {
        int dz = tap / 9 - 1, dy = (tap / 3) % 3 - 1, dx = tap % 3 - 1;
        __syncthreads();
        for (int j = tid; j < BGN; j += 256) {
            int ci = j / NGB, g = j - ci * NGB;
            const uint4* sh = reinterpret_cast<const uint4*>(
                Bhi + (size_t)tap * CIN * COUT + ci * COUT + g * 8);
            const uint4* sl = reinterpret_cast<const uint4*>(
                Blo + (size_t)tap * CIN * COUT + ci * COUT + g * 8);
            *reinterpret_cast<uint4*>(sBh + ci * LDB + g * 8) = *sh;
            *reinterpret_cast<uint4*>(sBl + ci * LDB + g * 8) = *sl;
        }
        for (int i = tid; i < 128 * KGA; i += 256) {
            int r = i / KGA, g = i - r * KGA;
            int k = g * 8;
            int o = o0 + r;
            int oz = o >> 12, oy = (o >> 6) & 63, ox = o & 63;
            int nz = oz + dz, ny = oy + dy, nx = ox + dx;
            bool ok = (unsigned)nz < (unsigned)GD1 && (unsigned)ny < (unsigned)GH1 &&
                      (unsigned)nx < (unsigned)GW1;
            uint4 vh = make_uint4(0u, 0u, 0u, 0u), vl = vh;
            if (ok) {
                size_t base = (size_t)((nz * GH1 + ny) * GW1 + nx) * (2 * CS) + k;
                vh = *reinterpret_cast<const uint4*>(X + base);
                vl = *reinterpret_cast<const uint4*>(X + base + CS);
            }
            *reinterpret_cast<uint4*>(sAh + r * LDA + k) = vh;
            *reinterpret_cast<uint4*>(sAl + r * LDA + k) = vl;
        }
        __syncthreads();
        const __nv_bfloat16* ah = sAh + wid * 16 * LDA;
        const __nv_bfloat16* al = sAl + wid * 16 * LDA;
#pragma unroll
        for (int kt = 0; kt < CIN / 16; kt++) {
            wmma::fragment<wmma::matrix_a, 16, 16, 16, __nv_bfloat16, wmma::row_major> fah, fal;
            wmma::load_matrix_sync(fah, ah + kt * 16, LDA);
            wmma::load_matrix_sync(fal, al + kt * 16, LDA);
#pragma unroll
            for (int nt = 0; nt < 6; nt++) {
                wmma::fragment<wmma::matrix_b, 16, 16, 16, __nv_bfloat16, wmma::row_major> fbh, fbl;
                wmma::load_matrix_sync(fbh, sBh + kt * 16 * LDB + nt * 16, LDB);
                wmma::load_matrix_sync(fbl, sBl + kt * 16 * LDB + nt * 16, LDB);
                wmma::mma_sync(acc[nt], fah, fbh, acc[nt]);
                wmma::mma_sync(acc[nt], fah, fbl, acc[nt]);
                wmma::mma_sync(acc[nt], fal, fbh, acc[nt]);
            }
        }
    }
    __syncthreads();
#pragma unroll
    for (int nt = 0; nt < 6; nt++)
        wmma::store_matrix_sync(sOut + wid * 16 * COUT + nt * 16, acc[nt], COUT,
                                wmma::mem_row_major);
    __syncthreads();
    if (OUT16) {
        for (int i = tid; i < 128 * 12; i += 256) {
            int r = i / 12, g = i - r * 12;
            int k = g * 8;
            float mv = mask[o0 + r];
            const float* s = sOut + r * COUT + k;
            float4 a = *reinterpret_cast<const float4*>(s);
            float4 b = *reinterpret_cast<const float4*>(s + 4);
            a.x *= mv; a.y *= mv; a.z *= mv; a.w *= mv;
            b.x *= mv; b.y *= mv; b.z *= mv; b.w *= mv;
            uint32_t h0, h1, h2, h3, l0, l1, l2, l3;
            packpair(a.x, a.y, h0, l0); packpair(a.z, a.w, h1, l1);
            packpair(b.x, b.y, h2, l2); packpair(b.z, b.w, h3, l3);
            size_t base = (size_t)(o0 + r) * (2 * CS) + k;
            *reinterpret_cast<uint4*>(Y16 + base) = make_uint4(h0, h1, h2, h3);
            *reinterpret_cast<uint4*>(Y16 + base + CS) = make_uint4(l0, l1, l2, l3);
        }
    } else {
        for (int i = tid; i < 128 * 24; i += 256) {
            int r = i / 24, c = i - r * 24;
            float mv = mask[o0 + r];
            float4 v = reinterpret_cast<const float4*>(sOut + r * COUT)[c];
            v.x *= mv; v.y *= mv; v.z *= mv; v.w *= mv;
            *reinterpret_cast<float4*>(&Yf[(size_t)(o0 + r) * CS + c * 4]) = v;
        }
    }
}

// ---------------- scalar decoder ----------------
__device__ __forceinline__ void fma4(float4& a, float4 w, float x) {
    a.x = fmaf(w.x, x, a.x);
    a.y = fmaf(w.y, x, a.y);
    a.z = fmaf(w.z, x, a.z);
    a.w = fmaf(w.w, x, a.w);
}

template <int CIN>
__device__ __forceinline__ void dotrow4(const float* __restrict__ w,
                                        const float* __restrict__ xv, float4& a) {
#pragma unroll
    for (int c = 0; c < CIN; c += 4) {
        float4 wv = *reinterpret_cast<const float4*>(w + c);
        float4 x4 = *reinterpret_cast<const float4*>(xv + c);
        a.x = fmaf(wv.x, x4.x, a.x);
        a.y = fmaf(wv.y, x4.y, a.y);
        a.z = fmaf(wv.z, x4.z, a.z);
        a.w = fmaf(wv.w, x4.w, a.w);
    }
}

// down1: k=2, s=2, tiled scalar (f32 -> f32)
__global__ void __launch_bounds__(192) conv_down1_kernel(
    const float* __restrict__ X, float* __restrict__ Y, const float* __restrict__ Wt) {
    constexpr int CIN = 96, COUT = 96, TM = 8;
    constexpr int TC = COUT / 4;
    constexpr int THREADS = TC * TM;
    constexpr int MT = TM * 8;
    constexpr int XPAD = MT + 4;
    constexpr int C4 = CIN / 4;
    __shared__ __align__(16) float xs[CIN * XPAD];
    int t = threadIdx.x;
    int o0 = blockIdx.x * MT;
    float4 acc[8];
#pragma unroll
    for (int j = 0; j < 8; j++) acc[j] = make_float4(0.f, 0.f, 0.f, 0.f);
    int tc = t % TC, tm = t / TC;

    for (int tap = 0; tap < 8; tap++) {
        int dz = tap >> 2, dy = (tap >> 1) & 1, dx = tap & 1;
        __syncthreads();
        for (int i = t; i < MT * C4; i += THREADS) {
            int m = i / C4, c4 = i - m * C4;
            int o = o0 + m;
            int oz = o >> 10, oy = (o >> 5) & 31, ox = o & 31;
            int nz = 2 * oz + dz, ny = 2 * oy + dy, nx = 2 * ox + dx;
            size_t base = (size_t)((nz * GH1 + ny) * GW1 + nx) * CS;
            float4 v = *reinterpret_cast<const float4*>(&X[base + c4 * 4]);
            xs[(c4 * 4 + 0) * XPAD + m] = v.x;
            xs[(c4 * 4 + 1) * XPAD + m] = v.y;
            xs[(c4 * 4 + 2) * XPAD + m] = v.z;
            xs[(c4 * 4 + 3) * XPAD + m] = v.w;
        }
        __syncthreads();
        const float* wp = Wt + (size_t)tap * CIN * COUT + tc * 4;
#pragma unroll 8
        for (int ci = 0; ci < CIN; ci++) {
            float4 w4 = *reinterpret_cast<const float4*>(wp + ci * COUT);
            float4 xa = *reinterpret_cast<const float4*>(xs + ci * XPAD + tm * 8);
            float4 xb = *reinterpret_cast<const float4*>(xs + ci * XPAD + tm * 8 + 4);
            fma4(acc[0], w4, xa.x); fma4(acc[1], w4, xa.y);
            fma4(acc[2], w4, xa.z); fma4(acc[3], w4, xa.w);
            fma4(acc[4], w4, xb.x); fma4(acc[5], w4, xb.y);
            fma4(acc[6], w4, xb.z); fma4(acc[7], w4, xb.w);
        }
    }
#pragma unroll
    for (int j = 0; j < 8; j++) {
        int m = tm * 8 + j;
        *reinterpret_cast<float4*>(&Y[(size_t)(o0 + m) * CS + tc * 4]) = acc[j];
    }
}

// inv1 tiled: block = one x-row of 64 outputs; 2 taps selected by parity.
__global__ void __launch_bounds__(128) inv1_tiled_kernel(
    const float* __restrict__ X2, float* __restrict__ Y,
    const float* __restrict__ W, const float* __restrict__ mask) {
    constexpr int SPAD = 33;
    __shared__ __align__(16) float xs[96 * SPAD];
    int t = threadIdx.x;
    int o0 = blockIdx.x * 64;
    int oz = o0 >> 12, oy = (o0 >> 6) & 63;
    int m0 = (((oz >> 1) * GH2) + (oy >> 1)) * GW2;
    int tapBase = ((oz & 1) * 2 + (oy & 1)) * 2;

    for (int i = t; i < 32 * 24; i += 128) {
        int s = i / 24, c4 = i - s * 24;
        float4 v = *reinterpret_cast<const float4*>(&X2[(size_t)(m0 + s) * CS + c4 * 4]);
        xs[(c4 * 4 + 0) * SPAD + s] = v.x;
        xs[(c4 * 4 + 1) * SPAD + s] = v.y;
        xs[(c4 * 4 + 2) * SPAD + s] = v.z;
        xs[(c4 * 4 + 3) * SPAD + s] = v.w;
    }
    __syncthreads();

    int tc = t & 15, tm = t >> 4;
    const float* wE = W + (size_t)tapBase * 96 * 64 + tc * 4;
    const float* wO = wE + 96 * 64;
    float4 acc[8];
#pragma unroll
    for (int j = 0; j < 8; j++) acc[j] = make_float4(0.f, 0.f, 0.f, 0.f);
#pragma unroll 4
    for (int ci = 0; ci < 96; ci++) {
        float4 we = *reinterpret_cast<const float4*>(wE + ci * 64);
        float4 wo = *reinterpret_cast<const float4*>(wO + ci * 64);
        float x0 = xs[ci * SPAD + tm * 4 + 0];
        float x1 = xs[ci * SPAD + tm * 4 + 1];
        float x2 = xs[ci * SPAD + tm * 4 + 2];
        float x3 = xs[ci * SPAD + tm * 4 + 3];
        fma4(acc[0], we, x0); fma4(acc[1], wo, x0);
        fma4(acc[2], we, x1); fma4(acc[3], wo, x1);
        fma4(acc[4], we, x2); fma4(acc[5], wo, x2);
        fma4(acc[6], we, x3); fma4(acc[7], wo, x3);
    }
#pragma unroll
    for (int j = 0; j < 8; j++) {
        int o = o0 + tm * 8 + j;
        float mv = mask[o];
        float4 r = acc[j];
        r.x *= mv; r.y *= mv; r.z *= mv; r.w *= mv;
        *reinterpret_cast<float4*>(&Y[(size_t)o * CS + tc * 4]) = r;
    }
}

// inv0: 8 points per block, one warp per point (repacked weights [tap][cout][cin])
__global__ void __launch_bounds__(256) inv0_kernel(
    const float* __restrict__ X, float* __restrict__ out,
    const int* __restrict__ coors, const float* __restrict__ Wt, int n) {
    constexpr int CIN = 64, COUT = 32;
    __shared__ __align__(16) float xs[8][CIN];
    int g = threadIdx.x >> 5, t = threadIdx.x & 31;
    int p = blockIdx.x * 8 + g;
    if (p >= n) return;
    int z = coors[p * 4 + 1], y = coors[p * 4 + 2], x = coors[p * 4 + 3];

    int mzv[2], wzv[2], myv[2], wyv[2], mxv[2], wxv[2];
    int nzc = 0, nyc = 0, nxc = 0;
    if ((z & 1) == 0) { mzv[0] = z >> 1; wzv[0] = 1; nzc = 1; }
    else {
        mzv[nzc] = z >> 1; wzv[nzc] = 2; nzc++;
        if ((z >> 1) + 1 < GD1) { mzv[nzc] = (z >> 1) + 1; wzv[nzc] = 0; nzc++; }
    }
    if ((y & 1) == 0) { myv[0] = y >> 1; wyv[0] = 1; nyc = 1; }
    else {
        myv[nyc] = y >> 1; wyv[nyc] = 2; nyc++;
        if ((y >> 1) + 1 < GH1) { myv[nyc] = (y >> 1) + 1; wyv[nyc] = 0; nyc++; }
    }
    if ((x & 1) == 0) { mxv[0] = x >> 1; wxv[0] = 1; nxc = 1; }
    else {
        mxv[nxc] = x >> 1; wxv[nxc] = 2; nxc++;
        if ((x >> 1) + 1 < GW1) { mxv[nxc] = (x >> 1) + 1; wxv[nxc] = 0; nxc++; }
    }

    float4 acc = make_float4(0.f, 0.f, 0.f, 0.f);
    for (int a = 0; a < nzc; a++)
        for (int b = 0; b < nyc; b++)
            for (int c = 0; c < nxc; c++) {
                int m = ((mzv[a] * GH1) + myv[b]) * GW1 + mxv[c];
                int tap = (wzv[a] * 3 + wyv[b]) * 3 + wxv[c];
                xs[g][t] = X[(size_t)m * CS + t];
                xs[g][t + 32] = X[(size_t)m * CS + t + 32];
                __syncwarp();
                dotrow4<CIN>(Wt + (tap * COUT + t) * CIN, xs[g], acc);
                __syncwarp();
            }
    out[(size_t)p * COUT + t] = acc.x + acc.y + acc.z + acc.w;
}

// ---------------- launch ----------------
extern "C" void kernel_launch(void* const* d_in, const int* in_sizes, int n_in,
                              void* d_out, int out_size) {
    const float* features = (const float*)d_in[0];
    const int* coors      = (const int*)d_in[1];
    int wb = n_in - 10;
    const float* w_sub0  = (const float*)d_in[wb + 0];
    const float* w_sub1  = (const float*)d_in[wb + 1];
    const float* w_sub2  = (const float*)d_in[wb + 2];
    const float* w_sub3  = (const float*)d_in[wb + 3];
    const float* w_down0 = (const float*)d_in[wb + 4];
    const float* w_sub4  = (const float*)d_in[wb + 5];
    const float* w_sub5  = (const float*)d_in[wb + 6];
    const float* w_down1 = (const float*)d_in[wb + 7];
    const float* w_inv1  = (const float*)d_in[wb + 8];
    const float* w_inv0  = (const float*)d_in[wb + 9];

    int n = in_sizes[0] / 3;

    float *fA, *cA, *c2p, *maskp, *pwi0;
    __nv_bfloat16 *fX, *fY, *cX, *cY;
    __nv_bfloat16 *b1h, *b1l, *b2h, *b2l, *b3h, *b3l, *bd0h, *bd0l, *b4h, *b4l, *b5h, *b5l;
    cudaGetSymbolAddress((void**)&fA, g_fineA);
    cudaGetSymbolAddress((void**)&cA, g_cA);
    cudaGetSymbolAddress((void**)&c2p, g_c2);
    cudaGetSymbolAddress((void**)&maskp, g_mask);
    cudaGetSymbolAddress((void**)&pwi0, g_wi0);
    cudaGetSymbolAddress((void**)&fX, g_fX);
    cudaGetSymbolAddress((void**)&fY, g_fY);
    cudaGetSymbolAddress((void**)&cX, g_cX);
    cudaGetSymbolAddress((void**)&cY, g_cY);
    cudaGetSymbolAddress((void**)&b1h, g_b1h);  cudaGetSymbolAddress((void**)&b1l, g_b1l);
    cudaGetSymbolAddress((void**)&b2h, g_b2h);  cudaGetSymbolAddress((void**)&b2l, g_b2l);
    cudaGetSymbolAddress((void**)&b3h, g_b3h);  cudaGetSymbolAddress((void**)&b3l, g_b3l);
    cudaGetSymbolAddress((void**)&bd0h, g_bd0h); cudaGetSymbolAddress((void**)&bd0l, g_bd0l);
    cudaGetSymbolAddress((void**)&b4h, g_b4h);  cudaGetSymbolAddress((void**)&b4l, g_b4l);
    cudaGetSymbolAddress((void**)&b5h, g_b5h);  cudaGetSymbolAddress((void**)&b5l, g_b5l);

    constexpr int SM_F3232 = 2 * 128 * 40 * 2 + 2 * 32 * 40 * 2;                    // 25600
    constexpr int SM_F3264 = 256 * 64 * 4;                                           // 65536
    constexpr int SM_F6464 = 2 * 256 * 72 * 2 + 2 * 64 * 72 * 2;                    // 92160
    constexpr int SM_D0    = 2 * 128 * 72 * 2 + 2 * 64 * 72 * 2;                    // 55296
    constexpr int SM_C64   = 2 * 128 * 72 * 2 + 2 * 64 * 104 * 2;                   // 63488
    constexpr int SM_C96   = 2 * 128 * 104 * 2 + 2 * 96 * 104 * 2;                  // 93184
    cudaFuncSetAttribute(conv_fine_wmma<32, 32, 128>, cudaFuncAttributeMaxDynamicSharedMemorySize, SM_F3232);
    cudaFuncSetAttribute(conv_fine_wmma<32, 64, 256>, cudaFuncAttributeMaxDynamicSharedMemorySize, SM_F3264);
    cudaFuncSetAttribute(conv_fine_wmma<64, 64, 256>, cudaFuncAttributeMaxDynamicSharedMemorySize, SM_F6464);
    cudaFuncSetAttribute(conv_down0_wmma, cudaFuncAttributeMaxDynamicSharedMemorySize, SM_D0);
    cudaFuncSetAttribute(conv_coarse_wmma<64, true>, cudaFuncAttributeMaxDynamicSharedMemorySize, SM_C64);
    cudaFuncSetAttribute(conv_coarse_wmma<96, false>, cudaFuncAttributeMaxDynamicSharedMemorySize, SM_C96);

    int nb128 = (n + 127) / 128;
    int nb256 = (n + 255) / 256;

    scatter_kernel<<<(n + 255) / 256, 256>>>(features, coors, fA, n);                         // 1
    bprep_kernel<<<(27 * 32 * 32 + 255) / 256, 256>>>(w_sub1, b1h, b1l, 27 * 32 * 32);        // 2
    conv_sub0_kernel<<<(n + 7) / 8, 256>>>(fA, fX, coors, w_sub0, n);                         // 3
    // launch 4: PROFILED slot
    conv_fine_wmma<32, 32, 128><<<nb128, 256, SM_F3232>>>(fX, fY, coors, b1h, b1l, n);        // 4
    bprep_kernel<<<(27 * 32 * 64 + 255) / 256, 256>>>(w_sub2, b2h, b2l, 27 * 32 * 64);        // 5
    conv_fine_wmma<32, 64, 256><<<nb256, 512, SM_F3264>>>(fY, fX, coors, b2h, b2l, n);        // 6
    bprep_kernel<<<(27 * 64 * 64 + 255) / 256, 256>>>(w_sub3, b3h, b3l, 27 * 64 * 64);        // 7
    conv_fine_wmma<64, 64, 256><<<nb256, 512, SM_F6464>>>(fX, fY, coors, b3h, b3l, n);        // 8
    mask_kernel<<<(n + 255) / 256, 256>>>(coors, maskp, n);                                   // 9
    bprep_kernel<<<(27 * 64 * 64 + 255) / 256, 256>>>(w_down0, bd0h, bd0l, 27 * 64 * 64);     // 10
    conv_down0_wmma<<<NC1 / 128, 256, SM_D0>>>(fY, cX, bd0h, bd0l);                           // 11
    bprep_kernel<<<(27 * 64 * 96 + 255) / 256, 256>>>(w_sub4, b4h, b4l, 27 * 64 * 96);        // 12
    bprep_kernel<<<(27 * 96 * 96 + 255) / 256, 256>>>(w_sub5, b5h, b5l, 27 * 96 * 96);        // 13
    conv_coarse_wmma<64, true><<<NC1 / 128, 256, SM_C64>>>(cX, nullptr, cY, b4h, b4l, maskp); // 14
    conv_coarse_wmma<96, false><<<NC1 / 128, 256, SM_C96>>>(cY, cA, nullptr, b5h, b5l, maskp);// 15
    conv_down1_kernel<<<NC2 / 64, 192>>>(cA, c2p, w_down1);                                   // 16
    repack_kernel<<<(27 * 64 * 32 + 255) / 256, 256>>>(w_inv0, pwi0, 27, 64, 32);             // 17
    inv1_tiled_kernel<<<NC1 / 64, 128>>>(c2p, cA, w_inv1, maskp);                             // 18
    inv0_kernel<<<(n + 7) / 8, 256>>>(cA, (float*)d_out, coors, pwi0, n);                     // 19
}

// round 14
// speedup vs baseline: 1.0174x; 1.0174x over previous
#include <cuda_runtime.h>
#include <cuda_bf16.h>
#include <mma.h>
#include <cstdint>

using namespace nvcuda;

// ---------------- geometry ----------------
#define GD0 27
#define GH0 127
#define GW0 127
#define NVOX (GD0*GH0*GW0)        // 435483
#define GD1 14
#define GH1 64
#define GW1 64
#define NC1 (GD1*GH1*GW1)         // 57344
#define GD2 7
#define GH2 32
#define GW2 32
#define NC2 (GD2*GH2*GW2)         // 7168
#define FS 64
#define CS 96
#define NVB ((NVOX + 4095) / 4096)   // 107

// ---------------- static scratch (zero-init; inactive voxels never written) ----
__device__ float g_fineA[(size_t)NVOX * 4];               // scatter input (3ch used)
__device__ float g_cA[NC1 * CS];
__device__ float g_c2[NC2 * CS];
__device__ float g_mask[NC1];
__device__ float g_wi0[27 * 32 * 64];
// point ordering
__device__ int g_vox2pt[NVOX];        // 0 = empty, else p+1 (same value each launch)
__device__ int g_order[1 << 17];
__device__ int g_blkCnt[NVB];
__device__ int g_blkOff[NVB];
// INTERLEAVED bf16 hi/lo activation buffers: per voxel [hi(FS) | lo(FS)]
__device__ __align__(256) __nv_bfloat16 g_fX[(size_t)NVOX * FS * 2];
__device__ __align__(256) __nv_bfloat16 g_fY[(size_t)NVOX * FS * 2];
__device__ __align__(256) __nv_bfloat16 g_cX[NC1 * CS * 2];
__device__ __align__(256) __nv_bfloat16 g_cY[NC1 * CS * 2];
// bf16 hi/lo weight images, ORIGINAL [tap][ci][co] layout
__device__ __align__(256) __nv_bfloat16 g_b1h[27 * 32 * 32],  g_b1l[27 * 32 * 32];
__device__ __align__(256) __nv_bfloat16 g_b2h[27 * 32 * 64],  g_b2l[27 * 32 * 64];
__device__ __align__(256) __nv_bfloat16 g_b3h[27 * 64 * 64],  g_b3l[27 * 64 * 64];
__device__ __align__(256) __nv_bfloat16 g_bd0h[27 * 64 * 64], g_bd0l[27 * 64 * 64];
__device__ __align__(256) __nv_bfloat16 g_b4h[27 * 64 * 96],  g_b4l[27 * 64 * 96];
__device__ __align__(256) __nv_bfloat16 g_b5h[27 * 96 * 96],  g_b5l[27 * 96 * 96];

// ---------------- helpers ----------------
__device__ __forceinline__ void packpair(float x, float y, uint32_t& h, uint32_t& l) {
    __nv_bfloat16 hx = __float2bfloat16(x), hy = __float2bfloat16(y);
    __nv_bfloat16 lx = __float2bfloat16(x - __bfloat162float(hx));
    __nv_bfloat16 ly = __float2bfloat16(y - __bfloat162float(hy));
    __nv_bfloat162 hh; hh.x = hx; hh.y = hy;
    __nv_bfloat162 ll; ll.x = lx; ll.y = ly;
    h = *reinterpret_cast<uint32_t*>(&hh);
    l = *reinterpret_cast<uint32_t*>(&ll);
}

__global__ void bprep_kernel(const float* __restrict__ W, __nv_bfloat16* __restrict__ hi,
                             __nv_bfloat16* __restrict__ lo, int tot) {
    int i = blockIdx.x * blockDim.x + threadIdx.x;
    if (i >= tot) return;
    float v = W[i];
    __nv_bfloat16 h = __float2bfloat16(v);
    hi[i] = h;
    lo[i] = __float2bfloat16(v - __bfloat162float(h));
}

__global__ void repack_kernel(const float* __restrict__ w, float* __restrict__ o,
                              int k3, int cin, int cout) {
    int i = blockIdx.x * blockDim.x + threadIdx.x;
    int tot = k3 * cin * cout;
    if (i >= tot) return;
    int co = i % cout;
    int r  = i / cout;
    int ci = r % cin;
    int t  = r / cin;
    o[(t * cout + co) * cin + ci] = w[i];
}

__global__ void scatter_kernel(const float* __restrict__ f, const int* __restrict__ coors,
                               float* __restrict__ X, int* __restrict__ v2p, int n) {
    int p = blockIdx.x * blockDim.x + threadIdx.x;
    if (p >= n) return;
    int z = coors[p * 4 + 1], y = coors[p * 4 + 2], x = coors[p * 4 + 3];
    int vi = (z * GH0 + y) * GW0 + x;
    size_t vox = (size_t)vi * 4;
    X[vox + 0] = f[p * 3 + 0];
    X[vox + 1] = f[p * 3 + 1];
    X[vox + 2] = f[p * 3 + 2];
    v2p[vi] = p + 1;
}

// ---------------- ordering: count / scan / compact (deterministic, sorted by voxel)
__global__ void count_kernel(const int* __restrict__ v2p, int* __restrict__ cnt) {
    __shared__ int sc[256];
    int b = blockIdx.x, t = threadIdx.x;
    int base = b * 4096 + t * 16;
    int c = 0;
#pragma unroll
    for (int j = 0; j < 16; j++) {
        int v = base + j;
        if (v < NVOX && v2p[v]) c++;
    }
    sc[t] = c;
    __syncthreads();
    for (int s = 128; s > 0; s >>= 1) {
        if (t < s) sc[t] += sc[t + s];
        __syncthreads();
    }
    if (t == 0) cnt[b] = sc[0];
}

__global__ void scan_kernel(const int* __restrict__ cnt, int* __restrict__ off) {
    if (threadIdx.x == 0) {
        int acc = 0;
        for (int b = 0; b < NVB; b++) { off[b] = acc; acc += cnt[b]; }
    }
}

__global__ void compact_kernel(const int* __restrict__ v2p, const int* __restrict__ off,
                               int* __restrict__ order) {
    __shared__ int so[257];
    int b = blockIdx.x, t = threadIdx.x;
    int base = b * 4096 + t * 16;
    int c = 0;
#pragma unroll
    for (int j = 0; j < 16; j++) {
        int v = base + j;
        if (v < NVOX && v2p[v]) c++;
    }
    so[t + 1] = c;
    __syncthreads();
    if (t == 0) {
        so[0] = off[b];
        for (int i = 1; i <= 256; i++) so[i] += so[i - 1];
    }
    __syncthreads();
    int w = so[t];
    for (int j = 0; j < 16; j++) {
        int v = base + j;
        if (v < NVOX) {
            int pv = v2p[v];
            if (pv) order[w++] = pv - 1;
        }
    }
}

__global__ void mask_kernel(const int* __restrict__ coors, float* __restrict__ mask, int n) {
    int p = blockIdx.x * blockDim.x + threadIdx.x;
    if (p >= n) return;
    int z = coors[p * 4 + 1], y = coors[p * 4 + 2], x = coors[p * 4 + 3];
    int zo[2], yo[2], xo[2];
    int nzc = 0, nyc = 0, nxc = 0;
    if ((z & 1) == 0) { zo[nzc++] = z >> 1; }
    else { zo[nzc++] = z >> 1; if ((z >> 1) + 1 < GD1) zo[nzc++] = (z >> 1) + 1; }
    if ((y & 1) == 0) { yo[nyc++] = y >> 1; }
    else { yo[nyc++] = y >> 1; if ((y >> 1) + 1 < GH1) yo[nyc++] = (y >> 1) + 1; }
    if ((x & 1) == 0) { xo[nxc++] = x >> 1; }
    else { xo[nxc++] = x >> 1; if ((x >> 1) + 1 < GW1) xo[nxc++] = (x >> 1) + 1; }
    for (int a = 0; a < nzc; a++)
        for (int b = 0; b < nyc; b++)
            for (int c = 0; c < nxc; c++)
                mask[(zo[a] * GH1 + yo[b]) * GW1 + xo[c]] = 1.0f;
}

// ---------------- sub0: 3->32, 8 points per block (one warp per point); ordered
__global__ void __launch_bounds__(256) conv_sub0_kernel(
    const float* __restrict__ X, __nv_bfloat16* __restrict__ Y,
    const int* __restrict__ coors, const int* __restrict__ order,
    const float* __restrict__ W, int n) {
    __shared__ float xs[8][84];
    int g = threadIdx.x >> 5, t = threadIdx.x & 31;
    int idx = blockIdx.x * 8 + g;
    if (idx >= n) return;
    int p = order[idx];
    int z = coors[p * 4 + 1], y = coors[p * 4 + 2], x = coors[p * 4 + 3];
    for (int i = t; i < 81; i += 32) {
        int tap = i / 3, ci = i % 3;
        int nz = z + tap / 9 - 1;
        int ny = y + (tap / 3) % 3 - 1;
        int nx = x + tap % 3 - 1;
        bool ok = (unsigned)nz < (unsigned)GD0 && (unsigned)ny < (unsigned)GH0 &&
                  (unsigned)nx < (unsigned)GW0;
        xs[g][i] = ok ? X[(size_t)((nz * GH0 + ny) * GW0 + nx) * 4 + ci] : 0.0f;
    }
    __syncwarp();
    float a = 0.f;
#pragma unroll
    for (int i = 0; i < 81; i++) a = fmaf(W[i * 32 + t], xs[g][i], a);
    size_t v = (size_t)((z * GH0 + y) * GW0 + x) * (2 * FS);
    __nv_bfloat16 h = __float2bfloat16(a);
    Y[v + t] = h;
    Y[v + FS + t] = __float2bfloat16(a - __bfloat162float(h));
}

// ---------------- fine submanifold conv via wmma, spatially ordered tiles
template <int CIN, int COUT, int MTILE>
__global__ void __launch_bounds__(MTILE * 2) conv_fine_wmma(
    const __nv_bfloat16* __restrict__ X, __nv_bfloat16* __restrict__ Y,
    const int* __restrict__ coors, const int* __restrict__ order,
    const __nv_bfloat16* __restrict__ Bhi, const __nv_bfloat16* __restrict__ Blo, int n) {
    constexpr int THREADS = MTILE * 2;
    constexpr int LDA = CIN + 8;
    constexpr int LDB = COUT + 8;
    constexpr int KGA = CIN / 8;
    constexpr int NGB = COUT / 8;
    constexpr int BGN = CIN * NGB;
    constexpr int NT = COUT / 16;
    __shared__ int s_z[MTILE], s_y[MTILE], s_x[MTILE];
    extern __shared__ __align__(256) char smem[];
    __nv_bfloat16* sAh = reinterpret_cast<__nv_bfloat16*>(smem);
    __nv_bfloat16* sAl = sAh + MTILE * LDA;
    __nv_bfloat16* sBh = sAl + MTILE * LDA;
    __nv_bfloat16* sBl = sBh + CIN * LDB;
    float* sOut = reinterpret_cast<float*>(smem);

    int tid = threadIdx.x, wid = tid >> 5;
    int p0 = blockIdx.x * MTILE;
    for (int i = tid; i < MTILE; i += THREADS) {
        int idx = p0 + i;
        int zz = -8, yy = 0, xv = 0;
        if (idx < n) {
            int p = order[idx];
            zz = coors[p * 4 + 1]; yy = coors[p * 4 + 2]; xv = coors[p * 4 + 3];
        }
        s_z[i] = zz; s_y[i] = yy; s_x[i] = xv;
    }

    wmma::fragment<wmma::accumulator, 16, 16, 16, float> acc[NT];
#pragma unroll
    for (int i = 0; i < NT; i++) wmma::fill_fragment(acc[i], 0.0f);

    for (int tap = 0; tap < 27; tap++) {
        int dz = tap / 9 - 1, dy = (tap / 3) % 3 - 1, dx = tap % 3 - 1;
        __syncthreads();
        for (int j = tid; j < BGN; j += THREADS) {
            int ci = j / NGB, g = j - ci * NGB;
            const uint4* sh = reinterpret_cast<const uint4*>(
                Bhi + (size_t)tap * CIN * COUT + ci * COUT + g * 8);
            const uint4* sl = reinterpret_cast<const uint4*>(
                Blo + (size_t)tap * CIN * COUT + ci * COUT + g * 8);
            *reinterpret_cast<uint4*>(sBh + ci * LDB + g * 8) = *sh;
            *reinterpret_cast<uint4*>(sBl + ci * LDB + g * 8) = *sl;
        }
        for (int i = tid; i < MTILE * KGA; i += THREADS) {
            int r = i / KGA, g = i - r * KGA;
            int k = g * 8;
            int nz = s_z[r] + dz, ny = s_y[r] + dy, nx = s_x[r] + dx;
            bool ok = (unsigned)nz < (unsigned)GD0 && (unsigned)ny < (unsigned)GH0 &&
                      (unsigned)nx < (unsigned)GW0;
            uint4 vh = make_uint4(0u, 0u, 0u, 0u), vl = vh;
            if (ok) {
                size_t base = (size_t)((nz * GH0 + ny) * GW0 + nx) * (2 * FS) + k;
                vh = *reinterpret_cast<const uint4*>(X + base);
                vl = *reinterpret_cast<const uint4*>(X + base + FS);
            }
            *reinterpret_cast<uint4*>(sAh + r * LDA + k) = vh;
            *reinterpret_cast<uint4*>(sAl + r * LDA + k) = vl;
        }
        __syncthreads();
        const __nv_bfloat16* ah = sAh + wid * 16 * LDA;
        const __nv_bfloat16* al = sAl + wid * 16 * LDA;
#pragma unroll
        for (int kt = 0; kt < CIN / 16; kt++) {
            wmma::fragment<wmma::matrix_a, 16, 16, 16, __nv_bfloat16, wmma::row_major> fah, fal;
            wmma::load_matrix_sync(fah, ah + kt * 16, LDA);
            wmma::load_matrix_sync(fal, al + kt * 16, LDA);
#pragma unroll
            for (int nt = 0; nt < NT; nt++) {
                wmma::fragment<wmma::matrix_b, 16, 16, 16, __nv_bfloat16, wmma::row_major> fbh, fbl;
                wmma::load_matrix_sync(fbh, sBh + kt * 16 * LDB + nt * 16, LDB);
                wmma::load_matrix_sync(fbl, sBl + kt * 16 * LDB + nt * 16, LDB);
                wmma::mma_sync(acc[nt], fah, fbh, acc[nt]);
                wmma::mma_sync(acc[nt], fah, fbl, acc[nt]);
                wmma::mma_sync(acc[nt], fal, fbh, acc[nt]);
            }
        }
    }
    __syncthreads();
#pragma unroll
    for (int nt = 0; nt < NT; nt++)
        wmma::store_matrix_sync(sOut + wid * 16 * COUT + nt * 16, acc[nt], COUT,
                                wmma::mem_row_major);
    __syncthreads();
    for (int i = tid; i < MTILE * NGB; i += THREADS) {
        int r = i / NGB, g = i - r * NGB;
        int k = g * 8;
        if (p0 + r >= n) continue;
        const float* s = sOut + r * COUT + k;
        float4 a = *reinterpret_cast<const float4*>(s);
        float4 b = *reinterpret_cast<const float4*>(s + 4);
        uint32_t h0, h1, h2, h3, l0, l1, l2, l3;
        packpair(a.x, a.y, h0, l0); packpair(a.z, a.w, h1, l1);
        packpair(b.x, b.y, h2, l2); packpair(b.z, b.w, h3, l3);
        size_t base = (size_t)((s_z[r] * GH0 + s_y[r]) * GW0 + s_x[r]) * (2 * FS) + k;
        *reinterpret_cast<uint4*>(Y + base) = make_uint4(h0, h1, h2, h3);
        *reinterpret_cast<uint4*>(Y + base + FS) = make_uint4(l0, l1, l2, l3);
    }
}

// ---------------- down0 via wmma: fine interleaved -> coarse interleaved (dense)
__global__ void __launch_bounds__(256) conv_down0_wmma(
    const __nv_bfloat16* __restrict__ X, __nv_bfloat16* __restrict__ Y,
    const __nv_bfloat16* __restrict__ Bhi, const __nv_bfloat16* __restrict__ Blo) {
    constexpr int CIN = 64, COUT = 64;
    constexpr int LDA = CIN + 8;
    constexpr int LDB = COUT + 8;
    constexpr int KGA = CIN / 8;
    constexpr int NGB = COUT / 8;
    constexpr int BGN = CIN * NGB;
    constexpr int NT = COUT / 16;
    extern __shared__ __align__(256) char smem[];
    __nv_bfloat16* sAh = reinterpret_cast<__nv_bfloat16*>(smem);
    __nv_bfloat16* sAl = sAh + 128 * LDA;
    __nv_bfloat16* sBh = sAl + 128 * LDA;
    __nv_bfloat16* sBl = sBh + CIN * LDB;
    float* sOut = reinterpret_cast<float*>(smem);

    int tid = threadIdx.x, wid = tid >> 5;
    int o0 = blockIdx.x * 128;

    wmma::fragment<wmma::accumulator, 16, 16, 16, float> acc[NT];
#pragma unroll
    for (int i = 0; i < NT; i++) wmma::fill_fragment(acc[i], 0.0f);

    for (int tap = 0; tap < 27; tap++) {
        int dz = tap / 9 - 1, dy = (tap / 3) % 3 - 1, dx = tap % 3 - 1;
        __syncthreads();
        for (int j = tid; j < BGN; j += 256) {
            int ci = j / NGB, g = j - ci * NGB;
            const uint4* sh = reinterpret_cast<const uint4*>(
                Bhi + (size_t)tap * CIN * COUT + ci * COUT + g * 8);
            const uint4* sl = reinterpret_cast<const uint4*>(
                Blo + (size_t)tap * CIN * COUT + ci * COUT + g * 8);
            *reinterpret_cast<uint4*>(sBh + ci * LDB + g * 8) = *sh;
            *reinterpret_cast<uint4*>(sBl + ci * LDB + g * 8) = *sl;
        }
        for (int i = tid; i < 128 * KGA; i += 256) {
            int r = i / KGA, g = i - r * KGA;
            int k = g * 8;
            int o = o0 + r;
            int oz = o >> 12, oy = (o >> 6) & 63, ox = o & 63;
            int nz = 2 * oz + dz, ny = 2 * oy + dy, nx = 2 * ox + dx;
            bool ok = (unsigned)nz < (unsigned)GD0 && (unsigned)ny < (unsigned)GH0 &&
                      (unsigned)nx < (unsigned)GW0;
            uint4 vh = make_uint4(0u, 0u, 0u, 0u), vl = vh;
            if (ok) {
                size_t base = (size_t)((nz * GH0 + ny) * GW0 + nx) * (2 * FS) + k;
                vh = *reinterpret_cast<const uint4*>(X + base);
                vl = *reinterpret_cast<const uint4*>(X + base + FS);
            }
            *reinterpret_cast<uint4*>(sAh + r * LDA + k) = vh;
            *reinterpret_cast<uint4*>(sAl + r * LDA + k) = vl;
        }
        __syncthreads();
        const __nv_bfloat16* ah = sAh + wid * 16 * LDA;
        const __nv_bfloat16* al = sAl + wid * 16 * LDA;
#pragma unroll
        for (int kt = 0; kt < CIN / 16; kt++) {
            wmma::fragment<wmma::matrix_a, 16, 16, 16, __nv_bfloat16, wmma::row_major> fah, fal;
            wmma::load_matrix_sync(fah, ah + kt * 16, LDA);
            wmma::load_matrix_sync(fal, al + kt * 16, LDA);
#pragma unroll
            for (int nt = 0; nt < NT; nt++) {
                wmma::fragment<wmma::matrix_b, 16, 16, 16, __nv_bfloat16, wmma::row_major> fbh, fbl;
                wmma::load_matrix_sync(fbh, sBh + kt * 16 * LDB + nt * 16, LDB);
                wmma::load_matrix_sync(fbl, sBl + kt * 16 * LDB + nt * 16, LDB);
                wmma::mma_sync(acc[nt], fah, fbh, acc[nt]);
                wmma::mma_sync(acc[nt], fah, fbl, acc[nt]);
                wmma::mma_sync(acc[nt], fal, fbh, acc[nt]);
            }
        }
    }
    __syncthreads();
#pragma unroll
    for (int nt = 0; nt < NT; nt++)
        wmma::store_matrix_sync(sOut + wid * 16 * COUT + nt * 16, acc[nt], COUT,
                                wmma::mem_row_major);
    __syncthreads();
    for (int i = tid; i < 128 * NGB; i += 256) {
        int r = i / NGB, g = i - r * NGB;
        int k = g * 8;
        const float* s = sOut + r * COUT + k;
        float4 a = *reinterpret_cast<const float4*>(s);
        float4 b = *reinterpret_cast<const float4*>(s + 4);
        uint32_t h0, h1, h2, h3, l0, l1, l2, l3;
        packpair(a.x, a.y, h0, l0); packpair(a.z, a.w, h1, l1);
        packpair(b.x, b.y, h2, l2); packpair(b.z, b.w, h3, l3);
        size_t base = (size_t)(o0 + r) * (2 * CS) + k;
        *reinterpret_cast<uint4*>(Y + base) = make_uint4(h0, h1, h2, h3);
        *reinterpret_cast<uint4*>(Y + base + CS) = make_uint4(l0, l1, l2, l3);
    }
}

// ---------------- wmma coarse conv (k=3,s=1,p=1), masked, interleaved input
template <int CIN, bool OUT16>
__global__ void __launch_bounds__(256) conv_coarse_wmma(
    const __nv_bfloat16* __restrict__ X,
    float* __restrict__ Yf, __nv_bfloat16* __restrict__ Y16,
    const __nv_bfloat16* __restrict__ Bhi, const __nv_bfloat16* __restrict__ Blo,
    const float* __restrict__ mask) {
    constexpr int COUT = 96;
    constexpr int LDA = CIN + 8;
    constexpr int LDB = COUT + 8;
    constexpr int KGA = CIN / 8;
    constexpr int NGB = COUT / 8;
    constexpr int BGN = CIN * NGB;
    extern __shared__ __align__(256) char smem[];
    __nv_bfloat16* sAh = reinterpret_cast<__nv_bfloat16*>(smem);
    __nv_bfloat16* sAl = sAh + 128 * LDA;
    __nv_bfloat16* sBh = sAl + 128 * LDA;
    __nv_bfloat16* sBl = sBh + CIN * LDB;
    float* sOut = reinterpret_cast<float*>(smem);

    int tid = threadIdx.x, wid = tid >> 5;
    int o0 = blockIdx.x * 128;

    wmma::fragment<wmma::accumulator, 16, 16, 16, float> acc[6];
#pragma unroll
    for (int i = 0; i < 6; i++) wmma::fill_fragment(acc[i], 0.0f);

    for (int tap = 0; tap < 27; tap++) {
        int dz = tap / 9 - 1, dy = (tap / 3) % 3 - 1, dx = tap % 3 - 1;
        __syncthreads();
        for (int j = tid; j < BGN; j += 256) {
            int ci = j / NGB, g = j - ci * NGB;
            const uint4* sh = reinterpret_cast<const uint4*>(
                Bhi + (size_t)tap * CIN * COUT + ci * COUT + g * 8);
            const uint4* sl = reinterpret_cast<const uint4*>(
                Blo + (size_t)tap * CIN * COUT + ci * COUT + g * 8);
            *reinterpret_cast<uint4*>(sBh + ci * LDB + g * 8) = *sh;
            *reinterpret_cast<uint4*>(sBl + ci * LDB + g * 8) = *sl;
        }
        for (int i = tid; i < 128 * KGA; i += 256) {
            int r = i / KGA, g = i - r * KGA;
            int k = g * 8;
            int o = o0 + r;
            int oz = o >> 12, oy = (o >> 6) & 63, ox = o & 63;
            int nz = oz + dz, ny = oy + dy, nx = ox + dx;
            bool ok = (unsigned)nz < (unsigned)GD1 && (unsigned)ny < (unsigned)GH1 &&
                      (unsigned)nx < (unsigned)GW1;
            uint4 vh = make_uint4(0u, 0u, 0u, 0u), vl = vh;
            if (ok) {
                size_t base = (size_t)((nz * GH1 + ny) * GW1 + nx) * (2 * CS) + k;
                vh = *reinterpret_cast<const uint4*>(X + base);
                vl = *reinterpret_cast<const uint4*>(X + base + CS);
            }
            *reinterpret_cast<uint4*>(sAh + r * LDA + k) = vh;
            *reinterpret_cast<uint4*>(sAl + r * LDA + k) = vl;
        }
        __syncthreads();
        const __nv_bfloat16* ah = sAh + wid * 16 * LDA;
        const __nv_bfloat16* al = sAl + wid * 16 * LDA;
#pragma unroll
        for (int kt = 0; kt < CIN / 16; kt++) {
            wmma::fragment<wmma::matrix_a, 16, 16, 16, __nv_bfloat16, wmma::row_major> fah, fal;
            wmma::load_matrix_sync(fah, ah + kt * 16, LDA);
            wmma::load_matrix_sync(fal, al + kt * 16, LDA);
#pragma unroll
            for (int nt = 0; nt < 6; nt++) {
                wmma::fragment<wmma::matrix_b, 16, 16, 16, __nv_bfloat16, wmma::row_major> fbh, fbl;
                wmma::load_matrix_sync(fbh, sBh + kt * 16 * LDB + nt * 16, LDB);
                wmma::load_matrix_sync(fbl, sBl + kt * 16 * LDB + nt * 16, LDB);
                wmma::mma_sync(acc[nt], fah, fbh, acc[nt]);
                wmma::mma_sync(acc[nt], fah, fbl, acc[nt]);
                wmma::mma_sync(acc[nt], fal, fbh, acc[nt]);
            }
        }
    }
    __syncthreads();
#pragma unroll
    for (int nt = 0; nt < 6; nt++)
        wmma::store_matrix_sync(sOut + wid * 16 * COUT + nt * 16, acc[nt], COUT,
                                wmma::mem_row_major);
    __syncthreads();
    if (OUT16) {
        for (int i = tid; i < 128 * 12; i += 256) {
            int r = i / 12, g = i - r * 12;
            int k = g * 8;
            float mv = mask[o0 + r];
            const float* s = sOut + r * COUT + k;
            float4 a = *reinterpret_cast<const float4*>(s);
            float4 b = *reinterpret_cast<const float4*>(s + 4);
            a.x *= mv; a.y *= mv; a.z *= mv; a.w *= mv;
            b.x *= mv; b.y *= mv; b.z *= mv; b.w *= mv;
            uint32_t h0, h1, h2, h3, l0, l1, l2, l3;
            packpair(a.x, a.y, h0, l0); packpair(a.z, a.w, h1, l1);
            packpair(b.x, b.y, h2, l2); packpair(b.z, b.w, h3, l3);
            size_t base = (size_t)(o0 + r) * (2 * CS) + k;
            *reinterpret_cast<uint4*>(Y16 + base) = make_uint4(h0, h1, h2, h3);
            *reinterpret_cast<uint4*>(Y16 + base + CS) = make_uint4(l0, l1, l2, l3);
        }
    } else {
        for (int i = tid; i < 128 * 24; i += 256) {
            int r = i / 24, c = i - r * 24;
            float mv = mask[o0 + r];
            float4 v = reinterpret_cast<const float4*>(sOut + r * COUT)[c];
            v.x *= mv; v.y *= mv; v.z *= mv; v.w *= mv;
            *reinterpret_cast<float4*>(&Yf[(size_t)(o0 + r) * CS + c * 4]) = v;
        }
    }
}

// ---------------- scalar decoder ----------------
__device__ __forceinline__ void fma4(float4& a, float4 w, float x) {
    a.x = fmaf(w.x, x, a.x);
    a.y = fmaf(w.y, x, a.y);
    a.z = fmaf(w.z, x, a.z);
    a.w = fmaf(w.w, x, a.w);
}

template <int CIN>
__device__ __forceinline__ void dotrow4(const float* __restrict__ w,
                                        const float* __restrict__ xv, float4& a) {
#pragma unroll
    for (int c = 0; c < CIN; c += 4) {
        float4 wv = *reinterpret_cast<const float4*>(w + c);
        float4 x4 = *reinterpret_cast<const float4*>(xv + c);
        a.x = fmaf(wv.x, x4.x, a.x);
        a.y = fmaf(wv.y, x4.y, a.y);
        a.z = fmaf(wv.z, x4.z, a.z);
        a.w = fmaf(wv.w, x4.w, a.w);
    }
}

// down1: k=2, s=2, tiled scalar (f32 -> f32)
__global__ void __launch_bounds__(192) conv_down1_kernel(
    const float* __restrict__ X, float* __restrict__ Y, const float* __restrict__ Wt) {
    constexpr int CIN = 96, COUT = 96, TM = 8;
    constexpr int TC = COUT / 4;
    constexpr int THREADS = TC * TM;
    constexpr int MT = TM * 8;
    constexpr int XPAD = MT + 4;
    constexpr int C4 = CIN / 4;
    __shared__ __align__(16) float xs[CIN * XPAD];
    int t = threadIdx.x;
    int o0 = blockIdx.x * MT;
    float4 acc[8];
#pragma unroll
    for (int j = 0; j < 8; j++) acc[j] = make_float4(0.f, 0.f, 0.f, 0.f);
    int tc = t % TC, tm = t / TC;

    for (int tap = 0; tap < 8; tap++) {
        int dz = tap >> 2, dy = (tap >> 1) & 1, dx = tap & 1;
        __syncthreads();
        for (int i = t; i < MT * C4; i += THREADS) {
            int m = i / C4, c4 = i - m * C4;
            int o = o0 + m;
            int oz = o >> 10, oy = (o >> 5) & 31, ox = o & 31;
            int nz = 2 * oz + dz, ny = 2 * oy + dy, nx = 2 * ox + dx;
            size_t base = (size_t)((nz * GH1 + ny) * GW1 + nx) * CS;
            float4 v = *reinterpret_cast<const float4*>(&X[base + c4 * 4]);
            xs[(c4 * 4 + 0) * XPAD + m] = v.x;
            xs[(c4 * 4 + 1) * XPAD + m] = v.y;
            xs[(c4 * 4 + 2) * XPAD + m] = v.z;
            xs[(c4 * 4 + 3) * XPAD + m] = v.w;
        }
        __syncthreads();
        const float* wp = Wt + (size_t)tap * CIN * COUT + tc * 4;
#pragma unroll 8
        for (int ci = 0; ci < CIN; ci++) {
            float4 w4 = *reinterpret_cast<const float4*>(wp + ci * COUT);
            float4 xa = *reinterpret_cast<const float4*>(xs + ci * XPAD + tm * 8);
            float4 xb = *reinterpret_cast<const float4*>(xs + ci * XPAD + tm * 8 + 4);
            fma4(acc[0], w4, xa.x); fma4(acc[1], w4, xa.y);
            fma4(acc[2], w4, xa.z); fma4(acc[3], w4, xa.w);
            fma4(acc[4], w4, xb.x); fma4(acc[5], w4, xb.y);
            fma4(acc[6], w4, xb.z); fma4(acc[7], w4, xb.w);
        }
    }
#pragma unroll
    for (int j = 0; j < 8; j++) {
        int m = tm * 8 + j;
        *reinterpret_cast<float4*>(&Y[(size_t)(o0 + m) * CS + tc * 4]) = acc[j];
    }
}

// inv1 tiled: block = one x-row of 64 outputs; 2 taps selected by parity.
__global__ void __launch_bounds__(128) inv1_tiled_kernel(
    const float* __restrict__ X2, float* __restrict__ Y,
    const float* __restrict__ W, const float* __restrict__ mask) {
    constexpr int SPAD = 33;
    __shared__ __align__(16) float xs[96 * SPAD];
    int t = threadIdx.x;
    int o0 = blockIdx.x * 64;
    int oz = o0 >> 12, oy = (o0 >> 6) & 63;
    int m0 = (((oz >> 1) * GH2) + (oy >> 1)) * GW2;
    int tapBase = ((oz & 1) * 2 + (oy & 1)) * 2;

    for (int i = t; i < 32 * 24; i += 128) {
        int s = i / 24, c4 = i - s * 24;
        float4 v = *reinterpret_cast<const float4*>(&X2[(size_t)(m0 + s) * CS + c4 * 4]);
        xs[(c4 * 4 + 0) * SPAD + s] = v.x;
        xs[(c4 * 4 + 1) * SPAD + s] = v.y;
        xs[(c4 * 4 + 2) * SPAD + s] = v.z;
        xs[(c4 * 4 + 3) * SPAD + s] = v.w;
    }
    __syncthreads();

    int tc = t & 15, tm = t >> 4;
    const float* wE = W + (size_t)tapBase * 96 * 64 + tc * 4;
    const float* wO = wE + 96 * 64;
    float4 acc[8];
#pragma unroll
    for (int j = 0; j < 8; j++) acc[j] = make_float4(0.f, 0.f, 0.f, 0.f);
#pragma unroll 4
    for (int ci = 0; ci < 96; ci++) {
        float4 we = *reinterpret_cast<const float4*>(wE + ci * 64);
        float4 wo = *reinterpret_cast<const float4*>(wO + ci * 64);
        float x0 = xs[ci * SPAD + tm * 4 + 0];
        float x1 = xs[ci * SPAD + tm * 4 + 1];
        float x2 = xs[ci * SPAD + tm * 4 + 2];
        float x3 = xs[ci * SPAD + tm * 4 + 3];
        fma4(acc[0], we, x0); fma4(acc[1], wo, x0);
        fma4(acc[2], we, x1); fma4(acc[3], wo, x1);
        fma4(acc[4], we, x2); fma4(acc[5], wo, x2);
        fma4(acc[6], we, x3); fma4(acc[7], wo, x3);
    }
#pragma unroll
    for (int j = 0; j < 8; j++) {
        int o = o0 + tm * 8 + j;
        float mv = mask[o];
        float4 r = acc[j];
        r.x *= mv; r.y *= mv; r.z *= mv; r.w *= mv;
        *reinterpret_cast<float4*>(&Y[(size_t)o * CS + tc * 4]) = r;
    }
}

// inv0: 8 points per block (ordered), one warp per point
__global__ void __launch_bounds__(256) inv0_kernel(
    const float* __restrict__ X, float* __restrict__ out,
    const int* __restrict__ coors, const int* __restrict__ order,
    const float* __restrict__ Wt, int n) {
    constexpr int CIN = 64, COUT = 32;
    __shared__ __align__(16) float xs[8][CIN];
    int g = threadIdx.x >> 5, t = threadIdx.x & 31;
    int idx = blockIdx.x * 8 + g;
    if (idx >= n) return;
    int p = order[idx];
    int z = coors[p * 4 + 1], y = coors[p * 4 + 2], x = coors[p * 4 + 3];

    int mzv[2], wzv[2], myv[2], wyv[2], mxv[2], wxv[2];
    int nzc = 0, nyc = 0, nxc = 0;
    if ((z & 1) == 0) { mzv[0] = z >> 1; wzv[0] = 1; nzc = 1; }
    else {
        mzv[nzc] = z >> 1; wzv[nzc] = 2; nzc++;
        if ((z >> 1) + 1 < GD1) { mzv[nzc] = (z >> 1) + 1; wzv[nzc] = 0; nzc++; }
    }
    if ((y & 1) == 0) { myv[0] = y >> 1; wyv[0] = 1; nyc = 1; }
    else {
        myv[nyc] = y >> 1; wyv[nyc] = 2; nyc++;
        if ((y >> 1) + 1 < GH1) { myv[nyc] = (y >> 1) + 1; wyv[nyc] = 0; nyc++; }
    }
    if ((x & 1) == 0) { mxv[0] = x >> 1; wxv[0] = 1; nxc = 1; }
    else {
        mxv[nxc] = x >> 1; wxv[nxc] = 2; nxc++;
        if ((x >> 1) + 1 < GW1) { mxv[nxc] = (x >> 1) + 1; wxv[nxc] = 0; nxc++; }
    }

    float4 acc = make_float4(0.f, 0.f, 0.f, 0.f);
    for (int a = 0; a < nzc; a++)
        for (int b = 0; b < nyc; b++)
            for (int c = 0; c < nxc; c++) {
                int m = ((mzv[a] * GH1) + myv[b]) * GW1 + mxv[c];
                int tap = (wzv[a] * 3 + wyv[b]) * 3 + wxv[c];
                xs[g][t] = X[(size_t)m * CS + t];
                xs[g][t + 32] = X[(size_t)m * CS + t + 32];
                __syncwarp();
                dotrow4<CIN>(Wt + (tap * COUT + t) * CIN, xs[g], acc);
                __syncwarp();
            }
    out[(size_t)p * COUT + t] = acc.x + acc.y + acc.z + acc.w;
}

// ---------------- launch ----------------
extern "C" void kernel_launch(void* const* d_in, const int* in_sizes, int n_in,
                              void* d_out, int out_size) {
    const float* features = (const float*)d_in[0];
    const int* coors      = (const int*)d_in[1];
    int wb = n_in - 10;
    const float* w_sub0  = (const float*)d_in[wb + 0];
    const float* w_sub1  = (const float*)d_in[wb + 1];
    const float* w_sub2  = (const float*)d_in[wb + 2];
    const float* w_sub3  = (const float*)d_in[wb + 3];
    const float* w_down0 = (const float*)d_in[wb + 4];
    const float* w_sub4  = (const float*)d_in[wb + 5];
    const float* w_sub5  = (const float*)d_in[wb + 6];
    const float* w_down1 = (const float*)d_in[wb + 7];
    const float* w_inv1  = (const float*)d_in[wb + 8];
    const float* w_inv0  = (const float*)d_in[wb + 9];

    int n = in_sizes[0] / 3;

    float *fA, *cA, *c2p, *maskp, *pwi0;
    int *v2p, *orderp, *blkCnt, *blkOff;
    __nv_bfloat16 *fX, *fY, *cX, *cY;
    __nv_bfloat16 *b1h, *b1l, *b2h, *b2l, *b3h, *b3l, *bd0h, *bd0l, *b4h, *b4l, *b5h, *b5l;
    cudaGetSymbolAddress((void**)&fA, g_fineA);
    cudaGetSymbolAddress((void**)&cA, g_cA);
    cudaGetSymbolAddress((void**)&c2p, g_c2);
    cudaGetSymbolAddress((void**)&maskp, g_mask);
    cudaGetSymbolAddress((void**)&pwi0, g_wi0);
    cudaGetSymbolAddress((void**)&v2p, g_vox2pt);
    cudaGetSymbolAddress((void**)&orderp, g_order);
    cudaGetSymbolAddress((void**)&blkCnt, g_blkCnt);
    cudaGetSymbolAddress((void**)&blkOff, g_blkOff);
    cudaGetSymbolAddress((void**)&fX, g_fX);
    cudaGetSymbolAddress((void**)&fY, g_fY);
    cudaGetSymbolAddress((void**)&cX, g_cX);
    cudaGetSymbolAddress((void**)&cY, g_cY);
    cudaGetSymbolAddress((void**)&b1h, g_b1h);  cudaGetSymbolAddress((void**)&b1l, g_b1l);
    cudaGetSymbolAddress((void**)&b2h, g_b2h);  cudaGetSymbolAddress((void**)&b2l, g_b2l);
    cudaGetSymbolAddress((void**)&b3h, g_b3h);  cudaGetSymbolAddress((void**)&b3l, g_b3l);
    cudaGetSymbolAddress((void**)&bd0h, g_bd0h); cudaGetSymbolAddress((void**)&bd0l, g_bd0l);
    cudaGetSymbolAddress((void**)&b4h, g_b4h);  cudaGetSymbolAddress((void**)&b4l, g_b4l);
    cudaGetSymbolAddress((void**)&b5h, g_b5h);  cudaGetSymbolAddress((void**)&b5l, g_b5l);

    constexpr int SM_F3232 = 2 * 128 * 40 * 2 + 2 * 32 * 40 * 2;                    // 25600
    constexpr int SM_F3264 = 256 * 64 * 4;                                           // 65536
    constexpr int SM_F6464 = 2 * 256 * 72 * 2 + 2 * 64 * 72 * 2;                    // 92160
    constexpr int SM_D0    = 2 * 128 * 72 * 2 + 2 * 64 * 72 * 2;                    // 55296
    constexpr int SM_C64   = 2 * 128 * 72 * 2 + 2 * 64 * 104 * 2;                   // 63488
    constexpr int SM_C96   = 2 * 128 * 104 * 2 + 2 * 96 * 104 * 2;                  // 93184
    cudaFuncSetAttribute(conv_fine_wmma<32, 32, 128>, cudaFuncAttributeMaxDynamicSharedMemorySize, SM_F3232);
    cudaFuncSetAttribute(conv_fine_wmma<32, 64, 256>, cudaFuncAttributeMaxDynamicSharedMemorySize, SM_F3264);
    cudaFuncSetAttribute(conv_fine_wmma<64, 64, 256>, cudaFuncAttributeMaxDynamicSharedMemorySize, SM_F6464);
    cudaFuncSetAttribute(conv_down0_wmma, cudaFuncAttributeMaxDynamicSharedMemorySize, SM_D0);
    cudaFuncSetAttribute(conv_coarse_wmma<64, true>, cudaFuncAttributeMaxDynamicSharedMemorySize, SM_C64);
    cudaFuncSetAttribute(conv_coarse_wmma<96, false>, cudaFuncAttributeMaxDynamicSharedMemorySize, SM_C96);

    int nb128 = (n + 127) / 128;
    int nb256 = (n + 255) / 256;

    scatter_kernel<<<(n + 255) / 256, 256>>>(features, coors, fA, v2p, n);                    // 1
    count_kernel<<<NVB, 256>>>(v2p, blkCnt);                                                  // 2
    scan_kernel<<<1, 32>>>(blkCnt, blkOff);                                                   // 3
    compact_kernel<<<NVB, 256>>>(v2p, blkOff, orderp);                                        // 4 (profiled)
    bprep_kernel<<<(27 * 32 * 32 + 255) / 256, 256>>>(w_sub1, b1h, b1l, 27 * 32 * 32);        // 5
    conv_sub0_kernel<<<(n + 7) / 8, 256>>>(fA, fX, coors, orderp, w_sub0, n);                 // 6
    conv_fine_wmma<32, 32, 128><<<nb128, 256, SM_F3232>>>(fX, fY, coors, orderp, b1h, b1l, n);// 7
    bprep_kernel<<<(27 * 32 * 64 + 255) / 256, 256>>>(w_sub2, b2h, b2l, 27 * 32 * 64);        // 8
    conv_fine_wmma<32, 64, 256><<<nb256, 512, SM_F3264>>>(fY, fX, coors, orderp, b2h, b2l, n);// 9
    bprep_kernel<<<(27 * 64 * 64 + 255) / 256, 256>>>(w_sub3, b3h, b3l, 27 * 64 * 64);        // 10
    conv_fine_wmma<64, 64, 256><<<nb256, 512, SM_F6464>>>(fX, fY, coors, orderp, b3h, b3l, n);// 11
    mask_kernel<<<(n + 255) / 256, 256>>>(coors, maskp, n);                                   // 12
    bprep_kernel<<<(27 * 64 * 64 + 255) / 256, 256>>>(w_down0, bd0h, bd0l, 27 * 64 * 64);     // 13
    conv_down0_wmma<<<NC1 / 128, 256, SM_D0>>>(fY, cX, bd0h, bd0l);                           // 14
    bprep_kernel<<<(27 * 64 * 96 + 255) / 256, 256>>>(w_sub4, b4h, b4l, 27 * 64 * 96);        // 15
    bprep_kernel<<<(27 * 96 * 96 + 255) / 256, 256>>>(w_sub5, b5h, b5l, 27 * 96 * 96);        // 16
    conv_coarse_wmma<64, true><<<NC1 / 128, 256, SM_C64>>>(cX, nullptr, cY, b4h, b4l, maskp); // 17
    conv_coarse_wmma<96, false><<<NC1 / 128, 256, SM_C96>>>(cY, cA, nullptr, b5h, b5l, maskp);// 18
    conv_down1_kernel<<<NC2 / 64, 192>>>(cA, c2p, w_down1);                                   // 19
    repack_kernel<<<(27 * 64 * 32 + 255) / 256, 256>>>(w_inv0, pwi0, 27, 64, 32);             // 20
    inv1_tiled_kernel<<<NC1 / 64, 128>>>(c2p, cA, w_inv1, maskp);                             // 21
    inv0_kernel<<<(n + 7) / 8, 256>>>(cA, (float*)d_out, coors, orderp, pwi0, n);             // 22
}

// round 15
// speedup vs baseline: 1.0179x; 1.0004x over previous
#include <cuda_runtime.h>
#include <cuda_bf16.h>
#include <mma.h>
#include <cstdint>

using namespace nvcuda;

// ---------------- geometry ----------------
#define GD0 27
#define GH0 127
#define GW0 127
#define NVOX (GD0*GH0*GW0)        // 435483
#define GD1 14
#define GH1 64
#define GW1 64
#define NC1 (GD1*GH1*GW1)         // 57344
#define GD2 7
#define GH2 32
#define GW2 32
#define NC2 (GD2*GH2*GW2)         // 7168
#define FS 64
#define CS 96
#define NVB ((NVOX + 4095) / 4096)   // 107

// ---------------- static scratch (zero-init; inactive voxels never written) ----
__device__ float g_fineA[(size_t)NVOX * 4];
__device__ float g_cA[NC1 * CS];
__device__ float g_c2[NC2 * CS];
__device__ float g_mask[NC1];
__device__ float g_wi0[27 * 32 * 64];
// point ordering
__device__ int g_vox2pt[NVOX];
__device__ int g_order[1 << 17];
__device__ int g_blkCnt[NVB];
__device__ int g_blkOff[NVB];
// INTERLEAVED bf16 hi/lo activation buffers: per voxel [hi | lo]
__device__ __align__(256) __nv_bfloat16 g_fX[(size_t)NVOX * FS * 2];
__device__ __align__(256) __nv_bfloat16 g_fY[(size_t)NVOX * FS * 2];
__device__ __align__(256) __nv_bfloat16 g_cX[NC1 * CS * 2];
__device__ __align__(256) __nv_bfloat16 g_cY[NC1 * CS * 2];
// bf16 hi/lo weight images, ORIGINAL [tap][ci][co] layout
__device__ __align__(256) __nv_bfloat16 g_b1h[27 * 32 * 32],  g_b1l[27 * 32 * 32];
__device__ __align__(256) __nv_bfloat16 g_b2h[27 * 32 * 64],  g_b2l[27 * 32 * 64];
__device__ __align__(256) __nv_bfloat16 g_b3h[27 * 64 * 64],  g_b3l[27 * 64 * 64];
__device__ __align__(256) __nv_bfloat16 g_bd0h[27 * 64 * 64], g_bd0l[27 * 64 * 64];
__device__ __align__(256) __nv_bfloat16 g_b4h[27 * 64 * 96],  g_b4l[27 * 64 * 96];
__device__ __align__(256) __nv_bfloat16 g_b5h[27 * 96 * 96],  g_b5l[27 * 96 * 96];

// ---------------- helpers ----------------
__device__ __forceinline__ void packpair(float x, float y, uint32_t& h, uint32_t& l) {
    __nv_bfloat16 hx = __float2bfloat16(x), hy = __float2bfloat16(y);
    __nv_bfloat16 lx = __float2bfloat16(x - __bfloat162float(hx));
    __nv_bfloat16 ly = __float2bfloat16(y - __bfloat162float(hy));
    __nv_bfloat162 hh; hh.x = hx; hh.y = hy;
    __nv_bfloat162 ll; ll.x = lx; ll.y = ly;
    h = *reinterpret_cast<uint32_t*>(&hh);
    l = *reinterpret_cast<uint32_t*>(&ll);
}

__global__ void bprep_kernel(const float* __restrict__ W, __nv_bfloat16* __restrict__ hi,
                             __nv_bfloat16* __restrict__ lo, int tot) {
    int i = blockIdx.x * blockDim.x + threadIdx.x;
    if (i >= tot) return;
    float v = W[i];
    __nv_bfloat16 h = __float2bfloat16(v);
    hi[i] = h;
    lo[i] = __float2bfloat16(v - __bfloat162float(h));
}

__global__ void repack_kernel(const float* __restrict__ w, float* __restrict__ o,
                              int k3, int cin, int cout) {
    int i = blockIdx.x * blockDim.x + threadIdx.x;
    int tot = k3 * cin * cout;
    if (i >= tot) return;
    int co = i % cout;
    int r  = i / cout;
    int ci = r % cin;
    int t  = r / cin;
    o[(t * cout + co) * cin + ci] = w[i];
}

__global__ void scatter_kernel(const float* __restrict__ f, const int* __restrict__ coors,
                               float* __restrict__ X, int* __restrict__ v2p, int n) {
    int p = blockIdx.x * blockDim.x + threadIdx.x;
    if (p >= n) return;
    int z = coors[p * 4 + 1], y = coors[p * 4 + 2], x = coors[p * 4 + 3];
    int vi = (z * GH0 + y) * GW0 + x;
    size_t vox = (size_t)vi * 4;
    X[vox + 0] = f[p * 3 + 0];
    X[vox + 1] = f[p * 3 + 1];
    X[vox + 2] = f[p * 3 + 2];
    v2p[vi] = p + 1;
}

// ---------------- ordering: count / scan / compact ----------------
__global__ void count_kernel(const int* __restrict__ v2p, int* __restrict__ cnt) {
    __shared__ int sc[256];
    int b = blockIdx.x, t = threadIdx.x;
    int base = b * 4096 + t * 16;
    int c = 0;
#pragma unroll
    for (int j = 0; j < 16; j++) {
        int v = base + j;
        if (v < NVOX && v2p[v]) c++;
    }
    sc[t] = c;
    __syncthreads();
    for (int s = 128; s > 0; s >>= 1) {
        if (t < s) sc[t] += sc[t + s];
        __syncthreads();
    }
    if (t == 0) cnt[b] = sc[0];
}

__global__ void scan_kernel(const int* __restrict__ cnt, int* __restrict__ off) {
    if (threadIdx.x == 0) {
        int acc = 0;
        for (int b = 0; b < NVB; b++) { off[b] = acc; acc += cnt[b]; }
    }
}

__global__ void compact_kernel(const int* __restrict__ v2p, const int* __restrict__ off,
                               int* __restrict__ order) {
    __shared__ int so[257];
    int b = blockIdx.x, t = threadIdx.x;
    int base = b * 4096 + t * 16;
    int c = 0;
#pragma unroll
    for (int j = 0; j < 16; j++) {
        int v = base + j;
        if (v < NVOX && v2p[v]) c++;
    }
    so[t + 1] = c;
    __syncthreads();
    if (t == 0) {
        so[0] = off[b];
        for (int i = 1; i <= 256; i++) so[i] += so[i - 1];
    }
    __syncthreads();
    int w = so[t];
    for (int j = 0; j < 16; j++) {
        int v = base + j;
        if (v < NVOX) {
            int pv = v2p[v];
            if (pv) order[w++] = pv - 1;
        }
    }
}

__global__ void mask_kernel(const int* __restrict__ coors, float* __restrict__ mask, int n) {
    int p = blockIdx.x * blockDim.x + threadIdx.x;
    if (p >= n) return;
    int z = coors[p * 4 + 1], y = coors[p * 4 + 2], x = coors[p * 4 + 3];
    int zo[2], yo[2], xo[2];
    int nzc = 0, nyc = 0, nxc = 0;
    if ((z & 1) == 0) { zo[nzc++] = z >> 1; }
    else { zo[nzc++] = z >> 1; if ((z >> 1) + 1 < GD1) zo[nzc++] = (z >> 1) + 1; }
    if ((y & 1) == 0) { yo[nyc++] = y >> 1; }
    else { yo[nyc++] = y >> 1; if ((y >> 1) + 1 < GH1) yo[nyc++] = (y >> 1) + 1; }
    if ((x & 1) == 0) { xo[nxc++] = x >> 1; }
    else { xo[nxc++] = x >> 1; if ((x >> 1) + 1 < GW1) xo[nxc++] = (x >> 1) + 1; }
    for (int a = 0; a < nzc; a++)
        for (int b = 0; b < nyc; b++)
            for (int c = 0; c < nxc; c++)
                mask[(zo[a] * GH1 + yo[b]) * GW1 + xo[c]] = 1.0f;
}

// ---------------- sub0: 3->32, 8 points per block; ordered, interleaved out
__global__ void __launch_bounds__(256) conv_sub0_kernel(
    const float* __restrict__ X, __nv_bfloat16* __restrict__ Y,
    const int* __restrict__ coors, const int* __restrict__ order,
    const float* __restrict__ W, int n) {
    __shared__ float xs[8][84];
    int g = threadIdx.x >> 5, t = threadIdx.x & 31;
    int idx = blockIdx.x * 8 + g;
    if (idx >= n) return;
    int p = order[idx];
    int z = coors[p * 4 + 1], y = coors[p * 4 + 2], x = coors[p * 4 + 3];
    for (int i = t; i < 81; i += 32) {
        int tap = i / 3, ci = i % 3;
        int nz = z + tap / 9 - 1;
        int ny = y + (tap / 3) % 3 - 1;
        int nx = x + tap % 3 - 1;
        bool ok = (unsigned)nz < (unsigned)GD0 && (unsigned)ny < (unsigned)GH0 &&
                  (unsigned)nx < (unsigned)GW0;
        xs[g][i] = ok ? X[(size_t)((nz * GH0 + ny) * GW0 + nx) * 4 + ci] : 0.0f;
    }
    __syncwarp();
    float a = 0.f;
#pragma unroll
    for (int i = 0; i < 81; i++) a = fmaf(W[i * 32 + t], xs[g][i], a);
    size_t v = (size_t)((z * GH0 + y) * GW0 + x) * (2 * FS);
    __nv_bfloat16 h = __float2bfloat16(a);
    Y[v + t] = h;
    Y[v + FS + t] = __float2bfloat16(a - __bfloat162float(h));
}

// ---------------- fine submanifold conv via wmma m32n8k16, MTILE=256, 8 warps
template <int CIN, int COUT>
__global__ void __launch_bounds__(256) conv_fine_wmma(
    const __nv_bfloat16* __restrict__ X, __nv_bfloat16* __restrict__ Y,
    const int* __restrict__ coors, const int* __restrict__ order,
    const __nv_bfloat16* __restrict__ Bhi, const __nv_bfloat16* __restrict__ Blo, int n) {
    constexpr int MTILE = 256;
    constexpr int THREADS = 256;
    constexpr int LDA = CIN + 8;
    constexpr int LDB = COUT + 8;
    constexpr int KGA = CIN / 8;
    constexpr int NGB = COUT / 8;
    constexpr int BGN = CIN * NGB;
    constexpr int NT = COUT / 8;
    __shared__ int s_z[MTILE], s_y[MTILE], s_x[MTILE];
    extern __shared__ __align__(256) char smem[];
    __nv_bfloat16* sAh = reinterpret_cast<__nv_bfloat16*>(smem);
    __nv_bfloat16* sAl = sAh + MTILE * LDA;
    __nv_bfloat16* sBh = sAl + MTILE * LDA;
    __nv_bfloat16* sBl = sBh + CIN * LDB;
    float* sOut = reinterpret_cast<float*>(smem);

    int tid = threadIdx.x, wid = tid >> 5;
    int p0 = blockIdx.x * MTILE;
    for (int i = tid; i < MTILE; i += THREADS) {
        int idx = p0 + i;
        int zz = -8, yy = 0, xv = 0;
        if (idx < n) {
            int p = order[idx];
            zz = coors[p * 4 + 1]; yy = coors[p * 4 + 2]; xv = coors[p * 4 + 3];
        }
        s_z[i] = zz; s_y[i] = yy; s_x[i] = xv;
    }

    wmma::fragment<wmma::accumulator, 32, 8, 16, float> acc[NT];
#pragma unroll
    for (int i = 0; i < NT; i++) wmma::fill_fragment(acc[i], 0.0f);

    for (int tap = 0; tap < 27; tap++) {
        int dz = tap / 9 - 1, dy = (tap / 3) % 3 - 1, dx = tap % 3 - 1;
        __syncthreads();
        for (int j = tid; j < BGN; j += THREADS) {
            int ci = j / NGB, g = j - ci * NGB;
            const uint4* sh = reinterpret_cast<const uint4*>(
                Bhi + (size_t)tap * CIN * COUT + ci * COUT + g * 8);
            const uint4* sl = reinterpret_cast<const uint4*>(
                Blo + (size_t)tap * CIN * COUT + ci * COUT + g * 8);
            *reinterpret_cast<uint4*>(sBh + ci * LDB + g * 8) = *sh;
            *reinterpret_cast<uint4*>(sBl + ci * LDB + g * 8) = *sl;
        }
        for (int i = tid; i < MTILE * KGA; i += THREADS) {
            int r = i / KGA, g = i - r * KGA;
            int k = g * 8;
            int nz = s_z[r] + dz, ny = s_y[r] + dy, nx = s_x[r] + dx;
            bool ok = (unsigned)nz < (unsigned)GD0 && (unsigned)ny < (unsigned)GH0 &&
                      (unsigned)nx < (unsigned)GW0;
            uint4 vh = make_uint4(0u, 0u, 0u, 0u), vl = vh;
            if (ok) {
                size_t base = (size_t)((nz * GH0 + ny) * GW0 + nx) * (2 * FS) + k;
                vh = *reinterpret_cast<const uint4*>(X + base);
                vl = *reinterpret_cast<const uint4*>(X + base + FS);
            }
            *reinterpret_cast<uint4*>(sAh + r * LDA + k) = vh;
            *reinterpret_cast<uint4*>(sAl + r * LDA + k) = vl;
        }
        __syncthreads();
        const __nv_bfloat16* ah = sAh + wid * 32 * LDA;
        const __nv_bfloat16* al = sAl + wid * 32 * LDA;
#pragma unroll
        for (int kt = 0; kt < CIN / 16; kt++) {
            wmma::fragment<wmma::matrix_a, 32, 8, 16, __nv_bfloat16, wmma::row_major> fah, fal;
            wmma::load_matrix_sync(fah, ah + kt * 16, LDA);
            wmma::load_matrix_sync(fal, al + kt * 16, LDA);
#pragma unroll
            for (int nt = 0; nt < NT; nt++) {
                wmma::fragment<wmma::matrix_b, 32, 8, 16, __nv_bfloat16, wmma::row_major> fbh, fbl;
                wmma::load_matrix_sync(fbh, sBh + kt * 16 * LDB + nt * 8, LDB);
                wmma::load_matrix_sync(fbl, sBl + kt * 16 * LDB + nt * 8, LDB);
                wmma::mma_sync(acc[nt], fah, fbh, acc[nt]);
                wmma::mma_sync(acc[nt], fah, fbl, acc[nt]);
                wmma::mma_sync(acc[nt], fal, fbh, acc[nt]);
            }
        }
    }
    __syncthreads();
#pragma unroll
    for (int nt = 0; nt < NT; nt++)
        wmma::store_matrix_sync(sOut + wid * 32 * COUT + nt * 8, acc[nt], COUT,
                                wmma::mem_row_major);
    __syncthreads();
    for (int i = tid; i < MTILE * NGB; i += THREADS) {
        int r = i / NGB, g = i - r * NGB;
        int k = g * 8;
        if (p0 + r >= n) continue;
        const float* s = sOut + r * COUT + k;
        float4 a = *reinterpret_cast<const float4*>(s);
        float4 b = *reinterpret_cast<const float4*>(s + 4);
        uint32_t h0, h1, h2, h3, l0, l1, l2, l3;
        packpair(a.x, a.y, h0, l0); packpair(a.z, a.w, h1, l1);
        packpair(b.x, b.y, h2, l2); packpair(b.z, b.w, h3, l3);
        size_t base = (size_t)((s_z[r] * GH0 + s_y[r]) * GW0 + s_x[r]) * (2 * FS) + k;
        *reinterpret_cast<uint4*>(Y + base) = make_uint4(h0, h1, h2, h3);
        *reinterpret_cast<uint4*>(Y + base + FS) = make_uint4(l0, l1, l2, l3);
    }
}

// ---------------- down0 via wmma m32n8k16: fine -> coarse interleaved (dense), MTILE=256
__global__ void __launch_bounds__(256) conv_down0_wmma(
    const __nv_bfloat16* __restrict__ X, __nv_bfloat16* __restrict__ Y,
    const __nv_bfloat16* __restrict__ Bhi, const __nv_bfloat16* __restrict__ Blo) {
    constexpr int CIN = 64, COUT = 64;
    constexpr int MTILE = 256;
    constexpr int LDA = CIN + 8;
    constexpr int LDB = COUT + 8;
    constexpr int KGA = CIN / 8;
    constexpr int NGB = COUT / 8;
    constexpr int BGN = CIN * NGB;
    constexpr int NT = COUT / 8;
    extern __shared__ __align__(256) char smem[];
    __nv_bfloat16* sAh = reinterpret_cast<__nv_bfloat16*>(smem);
    __nv_bfloat16* sAl = sAh + MTILE * LDA;
    __nv_bfloat16* sBh = sAl + MTILE * LDA;
    __nv_bfloat16* sBl = sBh + CIN * LDB;
    float* sOut = reinterpret_cast<float*>(smem);

    int tid = threadIdx.x, wid = tid >> 5;
    int o0 = blockIdx.x * MTILE;

    wmma::fragment<wmma::accumulator, 32, 8, 16, float> acc[NT];
#pragma unroll
    for (int i = 0; i < NT; i++) wmma::fill_fragment(acc[i], 0.0f);

    for (int tap = 0; tap < 27; tap++) {
        int dz = tap / 9 - 1, dy = (tap / 3) % 3 - 1, dx = tap % 3 - 1;
        __syncthreads();
        for (int j = tid; j < BGN; j += 256) {
            int ci = j / NGB, g = j - ci * NGB;
            const uint4* sh = reinterpret_cast<const uint4*>(
                Bhi + (size_t)tap * CIN * COUT + ci * COUT + g * 8);
            const uint4* sl = reinterpret_cast<const uint4*>(
                Blo + (size_t)tap * CIN * COUT + ci * COUT + g * 8);
            *reinterpret_cast<uint4*>(sBh + ci * LDB + g * 8) = *sh;
            *reinterpret_cast<uint4*>(sBl + ci * LDB + g * 8) = *sl;
        }
        for (int i = tid; i < MTILE * KGA; i += 256) {
            int r = i / KGA, g = i - r * KGA;
            int k = g * 8;
            int o = o0 + r;
            int oz = o >> 12, oy = (o >> 6) & 63, ox = o & 63;
            int nz = 2 * oz + dz, ny = 2 * oy + dy, nx = 2 * ox + dx;
            bool ok = (unsigned)nz < (unsigned)GD0 && (unsigned)ny < (unsigned)GH0 &&
                      (unsigned)nx < (unsigned)GW0;
            uint4 vh = make_uint4(0u, 0u, 0u, 0u), vl = vh;
            if (ok) {
                size_t base = (size_t)((nz * GH0 + ny) * GW0 + nx) * (2 * FS) + k;
                vh = *reinterpret_cast<const uint4*>(X + base);
                vl = *reinterpret_cast<const uint4*>(X + base + FS);
            }
            *reinterpret_cast<uint4*>(sAh + r * LDA + k) = vh;
            *reinterpret_cast<uint4*>(sAl + r * LDA + k) = vl;
        }
        __syncthreads();
        const __nv_bfloat16* ah = sAh + wid * 32 * LDA;
        const __nv_bfloat16* al = sAl + wid * 32 * LDA;
#pragma unroll
        for (int kt = 0; kt < CIN / 16; kt++) {
            wmma::fragment<wmma::matrix_a, 32, 8, 16, __nv_bfloat16, wmma::row_major> fah, fal;
            wmma::load_matrix_sync(fah, ah + kt * 16, LDA);
            wmma::load_matrix_sync(fal, al + kt * 16, LDA);
#pragma unroll
            for (int nt = 0; nt < NT; nt++) {
                wmma::fragment<wmma::matrix_b, 32, 8, 16, __nv_bfloat16, wmma::row_major> fbh, fbl;
                wmma::load_matrix_sync(fbh, sBh + kt * 16 * LDB + nt * 8, LDB);
                wmma::load_matrix_sync(fbl, sBl + kt * 16 * LDB + nt * 8, LDB);
                wmma::mma_sync(acc[nt], fah, fbh, acc[nt]);
                wmma::mma_sync(acc[nt], fah, fbl, acc[nt]);
                wmma::mma_sync(acc[nt], fal, fbh, acc[nt]);
            }
        }
    }
    __syncthreads();
#pragma unroll
    for (int nt = 0; nt < NT; nt++)
        wmma::store_matrix_sync(sOut + wid * 32 * COUT + nt * 8, acc[nt], COUT,
                                wmma::mem_row_major);
    __syncthreads();
    for (int i = tid; i < MTILE * NGB; i += 256) {
        int r = i / NGB, g = i - r * NGB;
        int k = g * 8;
        const float* s = sOut + r * COUT + k;
        float4 a = *reinterpret_cast<const float4*>(s);
        float4 b = *reinterpret_cast<const float4*>(s + 4);
        uint32_t h0, h1, h2, h3, l0, l1, l2, l3;
        packpair(a.x, a.y, h0, l0); packpair(a.z, a.w, h1, l1);
        packpair(b.x, b.y, h2, l2); packpair(b.z, b.w, h3, l3);
        size_t base = (size_t)(o0 + r) * (2 * CS) + k;
        *reinterpret_cast<uint4*>(Y + base) = make_uint4(h0, h1, h2, h3);
        *reinterpret_cast<uint4*>(Y + base + CS) = make_uint4(l0, l1, l2, l3);
    }
}

// ---------------- wmma coarse conv m32n8k16 (k=3,s=1,p=1), masked, MTILE=256
template <int CIN, bool OUT16>
__global__ void __launch_bounds__(256) conv_coarse_wmma(
    const __nv_bfloat16* __restrict__ X,
    float* __restrict__ Yf, __nv_bfloat16* __restrict__ Y16,
    const __nv_bfloat16* __restrict__ Bhi, const __nv_bfloat16* __restrict__ Blo,
    const float* __restrict__ mask) {
    constexpr int COUT = 96;
    constexpr int MTILE = 256;
    constexpr int LDA = CIN + 8;
    constexpr int LDB = COUT + 8;
    constexpr int KGA = CIN / 8;
    constexpr int NGB = COUT / 8;
    constexpr int BGN = CIN * NGB;
    constexpr int NT = COUT / 8;
    extern __shared__ __align__(256) char smem[];
    __nv_bfloat16* sAh = reinterpret_cast<__nv_bfloat16*>(smem);
    __nv_bfloat16* sAl = sAh + MTILE * LDA;
    __nv_bfloat16* sBh = sAl + MTILE * LDA;
    __nv_bfloat16* sBl = sBh + CIN * LDB;
    float* sOut = reinterpret_cast<float*>(smem);

    int tid = threadIdx.x, wid = tid >> 5;
    int o0 = blockIdx.x * MTILE;

    wmma::fragment<wmma::accumulator, 32, 8, 16, float> acc[NT];
#pragma unroll
    for (int i = 0; i < NT; i++) wmma::fill_fragment(acc[i], 0.0f);

    for (int tap = 0; tap < 27; tap++) {
        int dz = tap / 9 - 1, dy = (tap / 3) % 3 - 1, dx = tap % 3 - 1;
        __syncthreads();
        for (int j = tid; j < BGN; j += 256) {
            int ci = j / NGB, g = j - ci * NGB;
            const uint4* sh = reinterpret_cast<const uint4*>(
                Bhi + (size_t)tap * CIN * COUT + ci * COUT + g * 8);
            const uint4* sl = reinterpret_cast<const uint4*>(
                Blo + (size_t)tap * CIN * COUT + ci * COUT + g * 8);
            *reinterpret_cast<uint4*>(sBh + ci * LDB + g * 8) = *sh;
            *reinterpret_cast<uint4*>(sBl + ci * LDB + g * 8) = *sl;
        }
        for (int i = tid; i < MTILE * KGA; i += 256) {
            int r = i / KGA, g = i - r * KGA;
            int k = g * 8;
            int o = o0 + r;
            int oz = o >> 12, oy = (o >> 6) & 63, ox = o & 63;
            int nz = oz + dz, ny = oy + dy, nx = ox + dx;
            bool ok = (unsigned)nz < (unsigned)GD1 && (unsigned)ny < (unsigned)GH1 &&
                      (unsigned)nx < (unsigned)GW1;
            uint4 vh = make_uint4(0u, 0u, 0u, 0u), vl = vh;
            if (ok) {
                size_t base = (size_t)((nz * GH1 + ny) * GW1 + nx) * (2 * CS) + k;
                vh = *reinterpret_cast<const uint4*>(X + base);
                vl = *reinterpret_cast<const uint4*>(X + base + CS);
            }
            *reinterpret_cast<uint4*>(sAh + r * LDA + k) = vh;
            *reinterpret_cast<uint4*>(sAl + r * LDA + k) = vl;
        }
        __syncthreads();
        const __nv_bfloat16* ah = sAh + wid * 32 * LDA;
        const __nv_bfloat16* al = sAl + wid * 32 * LDA;
#pragma unroll
        for (int kt = 0; kt < CIN / 16; kt++) {
            wmma::fragment<wmma::matrix_a, 32, 8, 16, __nv_bfloat16, wmma::row_major> fah, fal;
            wmma::load_matrix_sync(fah, ah + kt * 16, LDA);
            wmma::load_matrix_sync(fal, al + kt * 16, LDA);
#pragma unroll
            for (int nt = 0; nt < NT; nt++) {
                wmma::fragment<wmma::matrix_b, 32, 8, 16, __nv_bfloat16, wmma::row_major> fbh, fbl;
                wmma::load_matrix_sync(fbh, sBh + kt * 16 * LDB + nt * 8, LDB);
                wmma::load_matrix_sync(fbl, sBl + kt * 16 * LDB + nt * 8, LDB);
                wmma::mma_sync(acc[nt], fah, fbh, acc[nt]);
                wmma::mma_sync(acc[nt], fah, fbl, acc[nt]);
                wmma::mma_sync(acc[nt], fal, fbh, acc[nt]);
            }
        }
    }
    __syncthreads();
#pragma unroll
    for (int nt = 0; nt < NT; nt++)
        wmma::store_matrix_sync(sOut + wid * 32 * COUT + nt * 8, acc[nt], COUT,
                                wmma::mem_row_major);
    __syncthreads();
    if (OUT16) {
        for (int i = tid; i < MTILE * 12; i += 256) {
            int r = i / 12, g = i - r * 12;
            int k = g * 8;
            float mv = mask[o0 + r];
            const float* s = sOut + r * COUT + k;
            float4 a = *reinterpret_cast<const float4*>(s);
            float4 b = *reinterpret_cast<const float4*>(s + 4);
            a.x *= mv; a.y *= mv; a.z *= mv; a.w *= mv;
            b.x *= mv; b.y *= mv; b.z *= mv; b.w *= mv;
            uint32_t h0, h1, h2, h3, l0, l1, l2, l3;
            packpair(a.x, a.y, h0, l0); packpair(a.z, a.w, h1, l1);
            packpair(b.x, b.y, h2, l2); packpair(b.z, b.w, h3, l3);
            size_t base = (size_t)(o0 + r) * (2 * CS) + k;
            *reinterpret_cast<uint4*>(Y16 + base) = make_uint4(h0, h1, h2, h3);
            *reinterpret_cast<uint4*>(Y16 + base + CS) = make_uint4(l0, l1, l2, l3);
        }
    } else {
        for (int i = tid; i < MTILE * 24; i += 256) {
            int r = i / 24, c = i - r * 24;
            float mv = mask[o0 + r];
            float4 v = reinterpret_cast<const float4*>(sOut + r * COUT)[c];
            v.x *= mv; v.y *= mv; v.z *= mv; v.w *= mv;
            *reinterpret_cast<float4*>(&Yf[(size_t)(o0 + r) * CS + c * 4]) = v;
        }
    }
}

// ---------------- scalar decoder ----------------
__device__ __forceinline__ void fma4(float4& a, float4 w, float x) {
    a.x = fmaf(w.x, x, a.x);
    a.y = fmaf(w.y, x, a.y);
    a.z = fmaf(w.z, x, a.z);
    a.w = fmaf(w.w, x, a.w);
}

template <int CIN>
__device__ __forceinline__ void dotrow4(const float* __restrict__ w,
                                        const float* __restrict__ xv, float4& a) {
#pragma unroll
    for (int c = 0; c < CIN; c += 4) {
        float4 wv = *reinterpret_cast<const float4*>(w + c);
        float4 x4 = *reinterpret_cast<const float4*>(xv + c);
        a.x = fmaf(wv.x, x4.x, a.x);
        a.y = fmaf(wv.y, x4.y, a.y);
        a.z = fmaf(wv.z, x4.z, a.z);
        a.w = fmaf(wv.w, x4.w, a.w);
    }
}

// down1: k=2, s=2, tiled scalar (f32 -> f32)
__global__ void __launch_bounds__(192) conv_down1_kernel(
    const float* __restrict__ X, float* __restrict__ Y, const float* __restrict__ Wt) {
    constexpr int CIN = 96, COUT = 96, TM = 8;
    constexpr int TC = COUT / 4;
    constexpr int THREADS = TC * TM;
    constexpr int MT = TM * 8;
    constexpr int XPAD = MT + 4;
    constexpr int C4 = CIN / 4;
    __shared__ __align__(16) float xs[CIN * XPAD];
    int t = threadIdx.x;
    int o0 = blockIdx.x * MT;
    float4 acc[8];
#pragma unroll
    for (int j = 0; j < 8; j++) acc[j] = make_float4(0.f, 0.f, 0.f, 0.f);
    int tc = t % TC, tm = t / TC;

    for (int tap = 0; tap < 8; tap++) {
        int dz = tap >> 2, dy = (tap >> 1) & 1, dx = tap & 1;
        __syncthreads();
        for (int i = t; i < MT * C4; i += THREADS) {
            int m = i / C4, c4 = i - m * C4;
            int o = o0 + m;
            int oz = o >> 10, oy = (o >> 5) & 31, ox = o & 31;
            int nz = 2 * oz + dz, ny = 2 * oy + dy, nx = 2 * ox + dx;
            size_t base = (size_t)((nz * GH1 + ny) * GW1 + nx) * CS;
            float4 v = *reinterpret_cast<const float4*>(&X[base + c4 * 4]);
            xs[(c4 * 4 + 0) * XPAD + m] = v.x;
            xs[(c4 * 4 + 1) * XPAD + m] = v.y;
            xs[(c4 * 4 + 2) * XPAD + m] = v.z;
            xs[(c4 * 4 + 3) * XPAD + m] = v.w;
        }
        __syncthreads();
        const float* wp = Wt + (size_t)tap * CIN * COUT + tc * 4;
#pragma unroll 8
        for (int ci = 0; ci < CIN; ci++) {
            float4 w4 = *reinterpret_cast<const float4*>(wp + ci * COUT);
            float4 xa = *reinterpret_cast<const float4*>(xs + ci * XPAD + tm * 8);
            float4 xb = *reinterpret_cast<const float4*>(xs + ci * XPAD + tm * 8 + 4);
            fma4(acc[0], w4, xa.x); fma4(acc[1], w4, xa.y);
            fma4(acc[2], w4, xa.z); fma4(acc[3], w4, xa.w);
            fma4(acc[4], w4, xb.x); fma4(acc[5], w4, xb.y);
            fma4(acc[6], w4, xb.z); fma4(acc[7], w4, xb.w);
        }
    }
#pragma unroll
    for (int j = 0; j < 8; j++) {
        int m = tm * 8 + j;
        *reinterpret_cast<float4*>(&Y[(size_t)(o0 + m) * CS + tc * 4]) = acc[j];
    }
}

// inv1 tiled: block = one x-row of 64 outputs; 2 taps selected by parity.
__global__ void __launch_bounds__(128) inv1_tiled_kernel(
    const float* __restrict__ X2, float* __restrict__ Y,
    const float* __restrict__ W, const float* __restrict__ mask) {
    constexpr int SPAD = 33;
    __shared__ __align__(16) float xs[96 * SPAD];
    int t = threadIdx.x;
    int o0 = blockIdx.x * 64;
    int oz = o0 >> 12, oy = (o0 >> 6) & 63;
    int m0 = (((oz >> 1) * GH2) + (oy >> 1)) * GW2;
    int tapBase = ((oz & 1) * 2 + (oy & 1)) * 2;

    for (int i = t; i < 32 * 24; i += 128) {
        int s = i / 24, c4 = i - s * 24;
        float4 v = *reinterpret_cast<const float4*>(&X2[(size_t)(m0 + s) * CS + c4 * 4]);
        xs[(c4 * 4 + 0) * SPAD + s] = v.x;
        xs[(c4 * 4 + 1) * SPAD + s] = v.y;
        xs[(c4 * 4 + 2) * SPAD + s] = v.z;
        xs[(c4 * 4 + 3) * SPAD + s] = v.w;
    }
    __syncthreads();

    int tc = t & 15, tm = t >> 4;
    const float* wE = W + (size_t)tapBase * 96 * 64 + tc * 4;
    const float* wO = wE + 96 * 64;
    float4 acc[8];
#pragma unroll
    for (int j = 0; j < 8; j++) acc[j] = make_float4(0.f, 0.f, 0.f, 0.f);
#pragma unroll 4
    for (int ci = 0; ci < 96; ci++) {
        float4 we = *reinterpret_cast<const float4*>(wE + ci * 64);
        float4 wo = *reinterpret_cast<const float4*>(wO + ci * 64);
        float x0 = xs[ci * SPAD + tm * 4 + 0];
        float x1 = xs[ci * SPAD + tm * 4 + 1];
        float x2 = xs[ci * SPAD + tm * 4 + 2];
        float x3 = xs[ci * SPAD + tm * 4 + 3];
        fma4(acc[0], we, x0); fma4(acc[1], wo, x0);
        fma4(acc[2], we, x1); fma4(acc[3], wo, x1);
        fma4(acc[4], we, x2); fma4(acc[5], wo, x2);
        fma4(acc[6], we, x3); fma4(acc[7], wo, x3);
    }
#pragma unroll
    for (int j = 0; j < 8; j++) {
        int o = o0 + tm * 8 + j;
        float mv = mask[o];
        float4 r = acc[j];
        r.x *= mv; r.y *= mv; r.z *= mv; r.w *= mv;
        *reinterpret_cast<float4*>(&Y[(size_t)o * CS + tc * 4]) = r;
    }
}

// inv0: 8 points per block (ordered), one warp per point
__global__ void __launch_bounds__(256) inv0_kernel(
    const float* __restrict__ X, float* __restrict__ out,
    const int* __restrict__ coors, const int* __restrict__ order,
    const float* __restrict__ Wt, int n) {
    constexpr int CIN = 64, COUT = 32;
    __shared__ __align__(16) float xs[8][CIN];
    int g = threadIdx.x >> 5, t = threadIdx.x & 31;
    int idx = blockIdx.x * 8 + g;
    if (idx >= n) return;
    int p = order[idx];
    int z = coors[p * 4 + 1], y = coors[p * 4 + 2], x = coors[p * 4 + 3];

    int mzv[2], wzv[2], myv[2], wyv[2], mxv[2], wxv[2];
    int nzc = 0, nyc = 0, nxc = 0;
    if ((z & 1) == 0) { mzv[0] = z >> 1; wzv[0] = 1; nzc = 1; }
    else {
        mzv[nzc] = z >> 1; wzv[nzc] = 2; nzc++;
        if ((z >> 1) + 1 < GD1) { mzv[nzc] = (z >> 1) + 1; wzv[nzc] = 0; nzc++; }
    }
    if ((y & 1) == 0) { myv[0] = y >> 1; wyv[0] = 1; nyc = 1; }
    else {
        myv[nyc] = y >> 1; wyv[nyc] = 2; nyc++;
        if ((y >> 1) + 1 < GH1) { myv[nyc] = (y >> 1) + 1; wyv[nyc] = 0; nyc++; }
    }
    if ((x & 1) == 0) { mxv[0] = x >> 1; wxv[0] = 1; nxc = 1; }
    else {
        mxv[nxc] = x >> 1; wxv[nxc] = 2; nxc++;
        if ((x >> 1) + 1 < GW1) { mxv[nxc] = (x >> 1) + 1; wxv[nxc] = 0; nxc++; }
    }

    float4 acc = make_float4(0.f, 0.f, 0.f, 0.f);
    for (int a = 0; a < nzc; a++)
        for (int b = 0; b < nyc; b++)
            for (int c = 0; c < nxc; c++) {
                int m = ((mzv[a] * GH1) + myv[b]) * GW1 + mxv[c];
                int tap = (wzv[a] * 3 + wyv[b]) * 3 + wxv[c];
                xs[g][t] = X[(size_t)m * CS + t];
                xs[g][t + 32] = X[(size_t)m * CS + t + 32];
                __syncwarp();
                dotrow4<CIN>(Wt + (tap * COUT + t) * CIN, xs[g], acc);
                __syncwarp();
            }
    out[(size_t)p * COUT + t] = acc.x + acc.y + acc.z + acc.w;
}

// ---------------- launch ----------------
extern "C" void kernel_launch(void* const* d_in, const int* in_sizes, int n_in,
                              void* d_out, int out_size) {
    const float* features = (const float*)d_in[0];
    const int* coors      = (const int*)d_in[1];
    int wb = n_in - 10;
    const float* w_sub0  = (const float*)d_in[wb + 0];
    const float* w_sub1  = (const float*)d_in[wb + 1];
    const float* w_sub2  = (const float*)d_in[wb + 2];
    const float* w_sub3  = (const float*)d_in[wb + 3];
    const float* w_down0 = (const float*)d_in[wb + 4];
    const float* w_sub4  = (const float*)d_in[wb + 5];
    const float* w_sub5  = (const float*)d_in[wb + 6];
    const float* w_down1 = (const float*)d_in[wb + 7];
    const float* w_inv1  = (const float*)d_in[wb + 8];
    const float* w_inv0  = (const float*)d_in[wb + 9];

    int n = in_sizes[0] / 3;

    float *fA, *cA, *c2p, *maskp, *pwi0;
    int *v2p, *orderp, *blkCnt, *blkOff;
    __nv_bfloat16 *fX, *fY, *cX, *cY;
    __nv_bfloat16 *b1h, *b1l, *b2h, *b2l, *b3h, *b3l, *bd0h, *bd0l, *b4h, *b4l, *b5h, *b5l;
    cudaGetSymbolAddress((void**)&fA, g_fineA);
    cudaGetSymbolAddress((void**)&cA, g_cA);
    cudaGetSymbolAddress((void**)&c2p, g_c2);
    cudaGetSymbolAddress((void**)&maskp, g_mask);
    cudaGetSymbolAddress((void**)&pwi0, g_wi0);
    cudaGetSymbolAddress((void**)&v2p, g_vox2pt);
    cudaGetSymbolAddress((void**)&orderp, g_order);
    cudaGetSymbolAddress((void**)&blkCnt, g_blkCnt);
    cudaGetSymbolAddress((void**)&blkOff, g_blkOff);
    cudaGetSymbolAddress((void**)&fX, g_fX);
    cudaGetSymbolAddress((void**)&fY, g_fY);
    cudaGetSymbolAddress((void**)&cX, g_cX);
    cudaGetSymbolAddress((void**)&cY, g_cY);
    cudaGetSymbolAddress((void**)&b1h, g_b1h);  cudaGetSymbolAddress((void**)&b1l, g_b1l);
    cudaGetSymbolAddress((void**)&b2h, g_b2h);  cudaGetSymbolAddress((void**)&b2l, g_b2l);
    cudaGetSymbolAddress((void**)&b3h, g_b3h);  cudaGetSymbolAddress((void**)&b3l, g_b3l);
    cudaGetSymbolAddress((void**)&bd0h, g_bd0h); cudaGetSymbolAddress((void**)&bd0l, g_bd0l);
    cudaGetSymbolAddress((void**)&b4h, g_b4h);  cudaGetSymbolAddress((void**)&b4l, g_b4l);
    cudaGetSymbolAddress((void**)&b5h, g_b5h);  cudaGetSymbolAddress((void**)&b5l, g_b5l);

    // dynamic smem (max of mainloop and out-tile reuse), MTILE=256
    constexpr int SM_F3232 = 2 * 256 * 40 * 2 + 2 * 32 * 40 * 2;    // 46080
    constexpr int SM_F3264 = 256 * 64 * 4;                           // 65536
    constexpr int SM_F6464 = 2 * 256 * 72 * 2 + 2 * 64 * 72 * 2;    // 92160
    constexpr int SM_C64   = 2 * 256 * 72 * 2 + 2 * 64 * 104 * 2;   // 100352
    constexpr int SM_C96   = 2 * 256 * 104 * 2 + 2 * 96 * 104 * 2;  // 146432
    cudaFuncSetAttribute(conv_fine_wmma<32, 32>, cudaFuncAttributeMaxDynamicSharedMemorySize, SM_F3232);
    cudaFuncSetAttribute(conv_fine_wmma<32, 64>, cudaFuncAttributeMaxDynamicSharedMemorySize, SM_F3264);
    cudaFuncSetAttribute(conv_fine_wmma<64, 64>, cudaFuncAttributeMaxDynamicSharedMemorySize, SM_F6464);
    cudaFuncSetAttribute(conv_down0_wmma, cudaFuncAttributeMaxDynamicSharedMemorySize, SM_F6464);
    cudaFuncSetAttribute(conv_coarse_wmma<64, true>, cudaFuncAttributeMaxDynamicSharedMemorySize, SM_C64);
    cudaFuncSetAttribute(conv_coarse_wmma<96, false>, cudaFuncAttributeMaxDynamicSharedMemorySize, SM_C96);

    int nb256 = (n + 255) / 256;

    scatter_kernel<<<(n + 255) / 256, 256>>>(features, coors, fA, v2p, n);                    // 1
    count_kernel<<<NVB, 256>>>(v2p, blkCnt);                                                  // 2
    scan_kernel<<<1, 32>>>(blkCnt, blkOff);                                                   // 3
    compact_kernel<<<NVB, 256>>>(v2p, blkOff, orderp);                                        // 4
    bprep_kernel<<<(27 * 32 * 32 + 255) / 256, 256>>>(w_sub1, b1h, b1l, 27 * 32 * 32);        // 5
    conv_sub0_kernel<<<(n + 7) / 8, 256>>>(fA, fX, coors, orderp, w_sub0, n);                 // 6
    conv_fine_wmma<32, 32><<<nb256, 256, SM_F3232>>>(fX, fY, coors, orderp, b1h, b1l, n);     // 7
    bprep_kernel<<<(27 * 32 * 64 + 255) / 256, 256>>>(w_sub2, b2h, b2l, 27 * 32 * 64);        // 8
    conv_fine_wmma<32, 64><<<nb256, 256, SM_F3264>>>(fY, fX, coors, orderp, b2h, b2l, n);     // 9
    bprep_kernel<<<(27 * 64 * 64 + 255) / 256, 256>>>(w_sub3, b3h, b3l, 27 * 64 * 64);        // 10
    conv_fine_wmma<64, 64><<<nb256, 256, SM_F6464>>>(fX, fY, coors, orderp, b3h, b3l, n);     // 11
    mask_kernel<<<(n + 255) / 256, 256>>>(coors, maskp, n);                                   // 12
    bprep_kernel<<<(27 * 64 * 64 + 255) / 256, 256>>>(w_down0, bd0h, bd0l, 27 * 64 * 64);     // 13
    conv_down0_wmma<<<NC1 / 256, 256, SM_F6464>>>(fY, cX, bd0h, bd0l);                        // 14
    bprep_kernel<<<(27 * 64 * 96 + 255) / 256, 256>>>(w_sub4, b4h, b4l, 27 * 64 * 96);        // 15
    bprep_kernel<<<(27 * 96 * 96 + 255) / 256, 256>>>(w_sub5, b5h, b5l, 27 * 96 * 96);        // 16
    conv_coarse_wmma<64, true><<<NC1 / 256, 256, SM_C64>>>(cX, nullptr, cY, b4h, b4l, maskp); // 17
    conv_coarse_wmma<96, false><<<NC1 / 256, 256, SM_C96>>>(cY, cA, nullptr, b5h, b5l, maskp);// 18
    conv_down1_kernel<<<NC2 / 64, 192>>>(cA, c2p, w_down1);                                   // 19
    repack_kernel<<<(27 * 64 * 32 + 255) / 256, 256>>>(w_inv0, pwi0, 27, 64, 32);             // 20
    inv1_tiled_kernel<<<NC1 / 64, 128>>>(c2p, cA, w_inv1, maskp);                             // 21
    inv0_kernel<<<(n + 7) / 8, 256>>>(cA, (float*)d_out, coors, orderp, pwi0, n);             // 22
}

// round 17
// speedup vs baseline: 1.2376x; 1.2159x over previous
#include <cuda_runtime.h>
#include <cuda_bf16.h>
#include <mma.h>
#include <cstdint>

using namespace nvcuda;

// ---------------- geometry ----------------
#define GD0 27
#define GH0 127
#define GW0 127
#define NVOX (GD0*GH0*GW0)        // 435483
#define GD1 14
#define GH1 64
#define GW1 64
#define NC1 (GD1*GH1*GW1)         // 57344
#define GD2 7
#define GH2 32
#define GW2 32
#define NC2 (GD2*GH2*GW2)         // 7168
#define FS 64
#define CS 96
#define NVB ((NVOX + 4095) / 4096)   // 107

// ---------------- static scratch (zero-init; inactive voxels never written) ----
__device__ float g_fineA[(size_t)NVOX * 4];
__device__ float g_cA[NC1 * CS];
__device__ float g_c2[NC2 * CS];
__device__ float g_mask[NC1];
__device__ float g_wi0[27 * 32 * 64];
__device__ int g_vox2pt[NVOX];
__device__ int g_order[1 << 17];
__device__ int g_blkCnt[NVB];
__device__ int g_blkOff[NVB];
// INTERLEAVED bf16 hi/lo activation buffers: per voxel [hi | lo]
__device__ __align__(256) __nv_bfloat16 g_fX[(size_t)NVOX * FS * 2];
__device__ __align__(256) __nv_bfloat16 g_fY[(size_t)NVOX * FS * 2];
__device__ __align__(256) __nv_bfloat16 g_cX[NC1 * CS * 2];
__device__ __align__(256) __nv_bfloat16 g_cY[NC1 * CS * 2];
// bf16 hi/lo weight images, ORIGINAL [tap][ci][co] layout
__device__ __align__(256) __nv_bfloat16 g_b1h[27 * 32 * 32],  g_b1l[27 * 32 * 32];
__device__ __align__(256) __nv_bfloat16 g_b2h[27 * 32 * 64],  g_b2l[27 * 32 * 64];
__device__ __align__(256) __nv_bfloat16 g_b3h[27 * 64 * 64],  g_b3l[27 * 64 * 64];
__device__ __align__(256) __nv_bfloat16 g_bd0h[27 * 64 * 64], g_bd0l[27 * 64 * 64];
__device__ __align__(256) __nv_bfloat16 g_b4h[27 * 64 * 96],  g_b4l[27 * 64 * 96];
__device__ __align__(256) __nv_bfloat16 g_b5h[27 * 96 * 96],  g_b5l[27 * 96 * 96];

// ---------------- helpers ----------------
__device__ __forceinline__ void cpa16(__nv_bfloat16* dst, const __nv_bfloat16* src, bool ok) {
    uint32_t d = (uint32_t)__cvta_generic_to_shared(dst);
    int sz = ok ? 16 : 0;
    asm volatile("cp.async.cg.shared.global [%0], [%1], 16, %2;"
                 :: "r"(d), "l"(src), "r"(sz) : "memory");
}
#define CPA_COMMIT() asm volatile("cp.async.commit_group;" ::: "memory")
#define CPA_WAIT1()  asm volatile("cp.async.wait_group 1;" ::: "memory")
#define CPA_WAIT0()  asm volatile("cp.async.wait_group 0;" ::: "memory")

__device__ __forceinline__ void packpair(float x, float y, uint32_t& h, uint32_t& l) {
    __nv_bfloat16 hx = __float2bfloat16(x), hy = __float2bfloat16(y);
    __nv_bfloat16 lx = __float2bfloat16(x - __bfloat162float(hx));
    __nv_bfloat16 ly = __float2bfloat16(y - __bfloat162float(hy));
    __nv_bfloat162 hh; hh.x = hx; hh.y = hy;
    __nv_bfloat162 ll; ll.x = lx; ll.y = ly;
    h = *reinterpret_cast<uint32_t*>(&hh);
    l = *reinterpret_cast<uint32_t*>(&ll);
}

__global__ void bprep_kernel(const float* __restrict__ W, __nv_bfloat16* __restrict__ hi,
                             __nv_bfloat16* __restrict__ lo, int tot) {
    int i = blockIdx.x * blockDim.x + threadIdx.x;
    if (i >= tot) return;
    float v = W[i];
    __nv_bfloat16 h = __float2bfloat16(v);
    hi[i] = h;
    lo[i] = __float2bfloat16(v - __bfloat162float(h));
}

__global__ void repack_kernel(const float* __restrict__ w, float* __restrict__ o,
                              int k3, int cin, int cout) {
    int i = blockIdx.x * blockDim.x + threadIdx.x;
    int tot = k3 * cin * cout;
    if (i >= tot) return;
    int co = i % cout;
    int r  = i / cout;
    int ci = r % cin;
    int t  = r / cin;
    o[(t * cout + co) * cin + ci] = w[i];
}

__global__ void scatter_kernel(const float* __restrict__ f, const int* __restrict__ coors,
                               float* __restrict__ X, int* __restrict__ v2p, int n) {
    int p = blockIdx.x * blockDim.x + threadIdx.x;
    if (p >= n) return;
    int z = coors[p * 4 + 1], y = coors[p * 4 + 2], x = coors[p * 4 + 3];
    int vi = (z * GH0 + y) * GW0 + x;
    size_t vox = (size_t)vi * 4;
    X[vox + 0] = f[p * 3 + 0];
    X[vox + 1] = f[p * 3 + 1];
    X[vox + 2] = f[p * 3 + 2];
    v2p[vi] = p + 1;
}

__global__ void count_kernel(const int* __restrict__ v2p, int* __restrict__ cnt) {
    __shared__ int sc[256];
    int b = blockIdx.x, t = threadIdx.x;
    int base = b * 4096 + t * 16;
    int c = 0;
#pragma unroll
    for (int j = 0; j < 16; j++) {
        int v = base + j;
        if (v < NVOX && v2p[v]) c++;
    }
    sc[t] = c;
    __syncthreads();
    for (int s = 128; s > 0; s >>= 1) {
        if (t < s) sc[t] += sc[t + s];
        __syncthreads();
    }
    if (t == 0) cnt[b] = sc[0];
}

__global__ void scan_kernel(const int* __restrict__ cnt, int* __restrict__ off) {
    if (threadIdx.x == 0) {
        int acc = 0;
        for (int b = 0; b < NVB; b++) { off[b] = acc; acc += cnt[b]; }
    }
}

__global__ void compact_kernel(const int* __restrict__ v2p, const int* __restrict__ off,
                               int* __restrict__ order) {
    __shared__ int so[257];
    int b = blockIdx.x, t = threadIdx.x;
    int base = b * 4096 + t * 16;
    int c = 0;
#pragma unroll
    for (int j = 0; j < 16; j++) {
        int v = base + j;
        if (v < NVOX && v2p[v]) c++;
    }
    so[t + 1] = c;
    __syncthreads();
    if (t == 0) {
        so[0] = off[b];
        for (int i = 1; i <= 256; i++) so[i] += so[i - 1];
    }
    __syncthreads();
    int w = so[t];
    for (int j = 0; j < 16; j++) {
        int v = base + j;
        if (v < NVOX) {
            int pv = v2p[v];
            if (pv) order[w++] = pv - 1;
        }
    }
}

__global__ void mask_kernel(const int* __restrict__ coors, float* __restrict__ mask, int n) {
    int p = blockIdx.x * blockDim.x + threadIdx.x;
    if (p >= n) return;
    int z = coors[p * 4 + 1], y = coors[p * 4 + 2], x = coors[p * 4 + 3];
    int zo[2], yo[2], xo[2];
    int nzc = 0, nyc = 0, nxc = 0;
    if ((z & 1) == 0) { zo[nzc++] = z >> 1; }
    else { zo[nzc++] = z >> 1; if ((z >> 1) + 1 < GD1) zo[nzc++] = (z >> 1) + 1; }
    if ((y & 1) == 0) { yo[nyc++] = y >> 1; }
    else { yo[nyc++] = y >> 1; if ((y >> 1) + 1 < GH1) yo[nyc++] = (y >> 1) + 1; }
    if ((x & 1) == 0) { xo[nxc++] = x >> 1; }
    else { xo[nxc++] = x >> 1; if ((x >> 1) + 1 < GW1) xo[nxc++] = (x >> 1) + 1; }
    for (int a = 0; a < nzc; a++)
        for (int b = 0; b < nyc; b++)
            for (int c = 0; c < nxc; c++)
                mask[(zo[a] * GH1 + yo[b]) * GW1 + xo[c]] = 1.0f;
}

// ---------------- sub0: 3->32, 8 points per block; ordered, interleaved out
__global__ void __launch_bounds__(256) conv_sub0_kernel(
    const float* __restrict__ X, __nv_bfloat16* __restrict__ Y,
    const int* __restrict__ coors, const int* __restrict__ order,
    const float* __restrict__ W, int n) {
    __shared__ float xs[8][84];
    int g = threadIdx.x >> 5, t = threadIdx.x & 31;
    int idx = blockIdx.x * 8 + g;
    if (idx >= n) return;
    int p = order[idx];
    int z = coors[p * 4 + 1], y = coors[p * 4 + 2], x = coors[p * 4 + 3];
    for (int i = t; i < 81; i += 32) {
        int tap = i / 3, ci = i % 3;
        int nz = z + tap / 9 - 1;
        int ny = y + (tap / 3) % 3 - 1;
        int nx = x + tap % 3 - 1;
        bool ok = (unsigned)nz < (unsigned)GD0 && (unsigned)ny < (unsigned)GH0 &&
                  (unsigned)nx < (unsigned)GW0;
        xs[g][i] = ok ? X[(size_t)((nz * GH0 + ny) * GW0 + nx) * 4 + ci] : 0.0f;
    }
    __syncwarp();
    float a = 0.f;
#pragma unroll
    for (int i = 0; i < 81; i++) a = fmaf(W[i * 32 + t], xs[g][i], a);
    size_t v = (size_t)((z * GH0 + y) * GW0 + x) * (2 * FS);
    __nv_bfloat16 h = __float2bfloat16(a);
    Y[v + t] = h;
    Y[v + FS + t] = __float2bfloat16(a - __bfloat162float(h));
}

// ---------------- fine submanifold conv: wmma m32n8k16, cp.async double-buffered
template <int CIN, int COUT, int MTILE>
__global__ void __launch_bounds__(256) conv_fine_wmma(
    const __nv_bfloat16* __restrict__ X, __nv_bfloat16* __restrict__ Y,
    const int* __restrict__ coors, const int* __restrict__ order,
    const __nv_bfloat16* __restrict__ Bhi, const __nv_bfloat16* __restrict__ Blo, int n) {
    constexpr int THREADS = 256;
    constexpr int LDA = CIN + 8;
    constexpr int LDB = COUT + 8;
    constexpr int KGA = CIN / 8;
    constexpr int NGB = COUT / 8;
    constexpr int BGN = CIN * NGB;
    constexpr int ASZ = MTILE * LDA;
    constexpr int BSZ = CIN * LDB;
    constexpr int NTH = (MTILE == 256) ? COUT / 8 : COUT / 16;
    __shared__ int s_z[MTILE], s_y[MTILE], s_x[MTILE];
    extern __shared__ __align__(256) char smem[];
    __nv_bfloat16* base = reinterpret_cast<__nv_bfloat16*>(smem);
    float* sOut = reinterpret_cast<float*>(smem);

    int tid = threadIdx.x, wid = tid >> 5;
    int p0 = blockIdx.x * MTILE;
    for (int i = tid; i < MTILE; i += THREADS) {
        int idx = p0 + i;
        int zz = -8, yy = 0, xv = 0;
        if (idx < n) {
            int p = order[idx];
            zz = coors[p * 4 + 1]; yy = coors[p * 4 + 2]; xv = coors[p * 4 + 3];
        }
        s_z[i] = zz; s_y[i] = yy; s_x[i] = xv;
    }
    __syncthreads();

    auto sA = [&](int b, int hl) { return base + (b * 2 + hl) * ASZ; };
    auto sB = [&](int b, int hl) { return base + 4 * ASZ + (b * 2 + hl) * BSZ; };

    auto stage = [&](int tap, int b) {
        const __nv_bfloat16* bh = Bhi + (size_t)tap * CIN * COUT;
        const __nv_bfloat16* bl = Blo + (size_t)tap * CIN * COUT;
        for (int j = tid; j < BGN; j += THREADS) {
            int ci = j / NGB, g = j - ci * NGB;
            cpa16(sB(b, 0) + ci * LDB + g * 8, bh + ci * COUT + g * 8, true);
            cpa16(sB(b, 1) + ci * LDB + g * 8, bl + ci * COUT + g * 8, true);
        }
        int dz = tap / 9 - 1, dy = (tap / 3) % 3 - 1, dx = tap % 3 - 1;
        for (int i = tid; i < MTILE * KGA; i += THREADS) {
            int r = i / KGA, g = i - r * KGA;
            int k = g * 8;
            int nz = s_z[r] + dz, ny = s_y[r] + dy, nx = s_x[r] + dx;
            bool ok = (unsigned)nz < (unsigned)GD0 && (unsigned)ny < (unsigned)GH0 &&
                      (unsigned)nx < (unsigned)GW0;
            size_t bb = ok ? (size_t)((nz * GH0 + ny) * GW0 + nx) * (2 * FS) + k : 0;
            cpa16(sA(b, 0) + r * LDA + k, X + bb, ok);
            cpa16(sA(b, 1) + r * LDA + k, X + bb + FS, ok);
        }
    };

    wmma::fragment<wmma::accumulator, 32, 8, 16, float> acc[NTH];
#pragma unroll
    for (int i = 0; i < NTH; i++) wmma::fill_fragment(acc[i], 0.0f);
    int wm = (MTILE == 256) ? wid : (wid & 3);
    int wn = (MTILE == 256) ? 0 : (wid >> 2);

    stage(0, 0);
    CPA_COMMIT();
    for (int tap = 0; tap < 27; tap++) {
        int cb = tap & 1;
        if (tap + 1 < 27) { stage(tap + 1, cb ^ 1); CPA_COMMIT(); CPA_WAIT1(); }
        else CPA_WAIT0();
        __syncthreads();
        const __nv_bfloat16* ah = sA(cb, 0) + wm * 32 * LDA;
        const __nv_bfloat16* al = sA(cb, 1) + wm * 32 * LDA;
#pragma unroll
        for (int kt = 0; kt < CIN / 16; kt++) {
            wmma::fragment<wmma::matrix_a, 32, 8, 16, __nv_bfloat16, wmma::row_major> fah, fal;
            wmma::load_matrix_sync(fah, ah + kt * 16, LDA);
            wmma::load_matrix_sync(fal, al + kt * 16, LDA);
#pragma unroll
            for (int nt = 0; nt < NTH; nt++) {
                int nc = (wn * NTH + nt) * 8;
                wmma::fragment<wmma::matrix_b, 32, 8, 16, __nv_bfloat16, wmma::row_major> fbh, fbl;
                wmma::load_matrix_sync(fbh, sB(cb, 0) + kt * 16 * LDB + nc, LDB);
                wmma::load_matrix_sync(fbl, sB(cb, 1) + kt * 16 * LDB + nc, LDB);
                wmma::mma_sync(acc[nt], fah, fbh, acc[nt]);
                wmma::mma_sync(acc[nt], fah, fbl, acc[nt]);
                wmma::mma_sync(acc[nt], fal, fbh, acc[nt]);
            }
        }
        __syncthreads();
    }
#pragma unroll
    for (int nt = 0; nt < NTH; nt++)
        wmma::store_matrix_sync(sOut + (wm * 32) * COUT + (wn * NTH + nt) * 8, acc[nt], COUT,
                                wmma::mem_row_major);
    __syncthreads();
    for (int i = tid; i < MTILE * NGB; i += THREADS) {
        int r = i / NGB, g = i - r * NGB;
        int k = g * 8;
        if (p0 + r >= n) continue;
        const float* s = sOut + r * COUT + k;
        float4 a = *reinterpret_cast<const float4*>(s);
        float4 b = *reinterpret_cast<const float4*>(s + 4);
        uint32_t h0, h1, h2, h3, l0, l1, l2, l3;
        packpair(a.x, a.y, h0, l0); packpair(a.z, a.w, h1, l1);
        packpair(b.x, b.y, h2, l2); packpair(b.z, b.w, h3, l3);
        size_t bo = (size_t)((s_z[r] * GH0 + s_y[r]) * GW0 + s_x[r]) * (2 * FS) + k;
        *reinterpret_cast<uint4*>(Y + bo) = make_uint4(h0, h1, h2, h3);
        *reinterpret_cast<uint4*>(Y + bo + FS) = make_uint4(l0, l1, l2, l3);
    }
}

// ---------------- dense wmma conv (down0 / coarse), cp.async double-buffered, MTILE=128
// MODE 0 = coarse subm (s=1, masked); 1 = down0 (fine->coarse s=2)
template <int CIN, int COUT, int MODE, bool OUT16>
__global__ void __launch_bounds__(256) conv_dense_wmma(
    const __nv_bfloat16* __restrict__ X,
    float* __restrict__ Yf, __nv_bfloat16* __restrict__ Y16,
    const __nv_bfloat16* __restrict__ Bhi, const __nv_bfloat16* __restrict__ Blo,
    const float* __restrict__ mask) {
    constexpr int MTILE = 128;
    constexpr int THREADS = 256;
    constexpr int LDA = CIN + 8;
    constexpr int LDB = COUT + 8;
    constexpr int KGA = CIN / 8;
    constexpr int NGB = COUT / 8;
    constexpr int BGN = CIN * NGB;
    constexpr int ASZ = MTILE * LDA;
    constexpr int BSZ = CIN * LDB;
    constexpr int NTH = COUT / 16;
    constexpr int XSTR = (MODE == 1) ? (2 * FS) : (2 * CS);
    extern __shared__ __align__(256) char smem[];
    __nv_bfloat16* base = reinterpret_cast<__nv_bfloat16*>(smem);
    float* sOut = reinterpret_cast<float*>(smem);

    int tid = threadIdx.x, wid = tid >> 5;
    int o0 = blockIdx.x * MTILE;

    auto sA = [&](int b, int hl) { return base + (b * 2 + hl) * ASZ; };
    auto sB = [&](int b, int hl) { return base + 4 * ASZ + (b * 2 + hl) * BSZ; };

    auto stage = [&](int tap, int b) {
        const __nv_bfloat16* bh = Bhi + (size_t)tap * CIN * COUT;
        const __nv_bfloat16* bl = Blo + (size_t)tap * CIN * COUT;
        for (int j = tid; j < BGN; j += THREADS) {
            int ci = j / NGB, g = j - ci * NGB;
            cpa16(sB(b, 0) + ci * LDB + g * 8, bh + ci * COUT + g * 8, true);
            cpa16(sB(b, 1) + ci * LDB + g * 8, bl + ci * COUT + g * 8, true);
        }
        int dz = tap / 9 - 1, dy = (tap / 3) % 3 - 1, dx = tap % 3 - 1;
        for (int i = tid; i < MTILE * KGA; i += THREADS) {
            int r = i / KGA, g = i - r * KGA;
            int k = g * 8;
            int o = o0 + r;
            int oz = o >> 12, oy = (o >> 6) & 63, ox = o & 63;
            int nz, ny, nx;
            bool ok;
            size_t bb;
            if (MODE == 1) {
                nz = 2 * oz + dz; ny = 2 * oy + dy; nx = 2 * ox + dx;
                ok = (unsigned)nz < (unsigned)GD0 && (unsigned)ny < (unsigned)GH0 &&
                     (unsigned)nx < (unsigned)GW0;
                bb = ok ? (size_t)((nz * GH0 + ny) * GW0 + nx) * XSTR + k : 0;
            } else {
                nz = oz + dz; ny = oy + dy; nx = ox + dx;
                ok = (unsigned)nz < (unsigned)GD1 && (unsigned)ny < (unsigned)GH1 &&
                     (unsigned)nx < (unsigned)GW1;
                bb = ok ? (size_t)((nz * GH1 + ny) * GW1 + nx) * XSTR + k : 0;
            }
            cpa16(sA(b, 0) + r * LDA + k, X + bb, ok);
            cpa16(sA(b, 1) + r * LDA + k, X + bb + XSTR / 2, ok);
        }
    };

    wmma::fragment<wmma::accumulator, 32, 8, 16, float> acc[NTH];
#pragma unroll
    for (int i = 0; i < NTH; i++) wmma::fill_fragment(acc[i], 0.0f);
    int wm = wid & 3, wn = wid >> 2;

    stage(0, 0);
    CPA_COMMIT();
    for (int tap = 0; tap < 27; tap++) {
        int cb = tap & 1;
        if (tap + 1 < 27) { stage(tap + 1, cb ^ 1); CPA_COMMIT(); CPA_WAIT1(); }
        else CPA_WAIT0();
        __syncthreads();
        const __nv_bfloat16* ah = sA(cb, 0) + wm * 32 * LDA;
        const __nv_bfloat16* al = sA(cb, 1) + wm * 32 * LDA;
#pragma unroll
        for (int kt = 0; kt < CIN / 16; kt++) {
            wmma::fragment<wmma::matrix_a, 32, 8, 16, __nv_bfloat16, wmma::row_major> fah, fal;
            wmma::load_matrix_sync(fah, ah + kt * 16, LDA);
            wmma::load_matrix_sync(fal, al + kt * 16, LDA);
#pragma unroll
            for (int nt = 0; nt < NTH; nt++) {
                int nc = (wn * NTH + nt) * 8;
                wmma::fragment<wmma::matrix_b, 32, 8, 16, __nv_bfloat16, wmma::row_major> fbh, fbl;
                wmma::load_matrix_sync(fbh, sB(cb, 0) + kt * 16 * LDB + nc, LDB);
                wmma::load_matrix_sync(fbl, sB(cb, 1) + kt * 16 * LDB + nc, LDB);
                wmma::mma_sync(acc[nt], fah, fbh, acc[nt]);
                wmma::mma_sync(acc[nt], fah, fbl, acc[nt]);
                wmma::mma_sync(acc[nt], fal, fbh, acc[nt]);
            }
        }
        __syncthreads();
    }
#pragma unroll
    for (int nt = 0; nt < NTH; nt++)
        wmma::store_matrix_sync(sOut + (wm * 32) * COUT + (wn * NTH + nt) * 8, acc[nt], COUT,
                                wmma::mem_row_major);
    __syncthreads();
    for (int i = tid; i < MTILE * NGB; i += THREADS) {
        int r = i / NGB, g = i - r * NGB;
        int k = g * 8;
        float mv = (MODE == 0) ? mask[o0 + r] : 1.0f;
        const float* s = sOut + r * COUT + k;
        float4 a = *reinterpret_cast<const float4*>(s);
        float4 b = *reinterpret_cast<const float4*>(s + 4);
        a.x *= mv; a.y *= mv; a.z *= mv; a.w *= mv;
        b.x *= mv; b.y *= mv; b.z *= mv; b.w *= mv;
        if (OUT16) {
            uint32_t h0, h1, h2, h3, l0, l1, l2, l3;
            packpair(a.x, a.y, h0, l0); packpair(a.z, a.w, h1, l1);
            packpair(b.x, b.y, h2, l2); packpair(b.z, b.w, h3, l3);
            size_t bo = (size_t)(o0 + r) * (2 * CS) + k;
            *reinterpret_cast<uint4*>(Y16 + bo) = make_uint4(h0, h1, h2, h3);
            *reinterpret_cast<uint4*>(Y16 + bo + CS) = make_uint4(l0, l1, l2, l3);
        } else {
            float* d = Yf + (size_t)(o0 + r) * CS + k;
            *reinterpret_cast<float4*>(d) = a;
            *reinterpret_cast<float4*>(d + 4) = b;
        }
    }
}

// ---------------- scalar decoder ----------------
__device__ __forceinline__ void fma4(float4& a, float4 w, float x) {
    a.x = fmaf(w.x, x, a.x);
    a.y = fmaf(w.y, x, a.y);
    a.z = fmaf(w.z, x, a.z);
    a.w = fmaf(w.w, x, a.w);
}

template <int CIN>
__device__ __forceinline__ void dotrow4(const float* __restrict__ w,
                                        const float* __restrict__ xv, float4& a) {
#pragma unroll
    for (int c = 0; c < CIN; c += 4) {
        float4 wv = *reinterpret_cast<const float4*>(w + c);
        float4 x4 = *reinterpret_cast<const float4*>(xv + c);
        a.x = fmaf(wv.x, x4.x, a.x);
        a.y = fmaf(wv.y, x4.y, a.y);
        a.z = fmaf(wv.z, x4.z, a.z);
        a.w = fmaf(wv.w, x4.w, a.w);
    }
}

__global__ void __launch_bounds__(192) conv_down1_kernel(
    const float* __restrict__ X, float* __restrict__ Y, const float* __restrict__ Wt) {
    constexpr int CIN = 96, COUT = 96, TM = 8;
    constexpr int TC = COUT / 4;
    constexpr int THREADS = TC * TM;
    constexpr int MT = TM * 8;
    constexpr int XPAD = MT + 4;
    constexpr int C4 = CIN / 4;
    __shared__ __align__(16) float xs[CIN * XPAD];
    int t = threadIdx.x;
    int o0 = blockIdx.x * MT;
    float4 acc[8];
#pragma unroll
    for (int j = 0; j < 8; j++) acc[j] = make_float4(0.f, 0.f, 0.f, 0.f);
    int tc = t % TC, tm = t / TC;

    for (int tap = 0; tap < 8; tap++) {
        int dz = tap >> 2, dy = (tap >> 1) & 1, dx = tap & 1;
        __syncthreads();
        for (int i = t; i < MT * C4; i += THREADS) {
            int m = i / C4, c4 = i - m * C4;
            int o = o0 + m;
            int oz = o >> 10, oy = (o >> 5) & 31, ox = o & 31;
            int nz = 2 * oz + dz, ny = 2 * oy + dy, nx = 2 * ox + dx;
            size_t base = (size_t)((nz * GH1 + ny) * GW1 + nx) * CS;
            float4 v = *reinterpret_cast<const float4*>(&X[base + c4 * 4]);
            xs[(c4 * 4 + 0) * XPAD + m] = v.x;
            xs[(c4 * 4 + 1) * XPAD + m] = v.y;
            xs[(c4 * 4 + 2) * XPAD + m] = v.z;
            xs[(c4 * 4 + 3) * XPAD + m] = v.w;
        }
        __syncthreads();
        const float* wp = Wt + (size_t)tap * CIN * COUT + tc * 4;
#pragma unroll 8
        for (int ci = 0; ci < CIN; ci++) {
            float4 w4 = *reinterpret_cast<const float4*>(wp + ci * COUT);
            float4 xa = *reinterpret_cast<const float4*>(xs + ci * XPAD + tm * 8);
            float4 xb = *reinterpret_cast<const float4*>(xs + ci * XPAD + tm * 8 + 4);
            fma4(acc[0], w4, xa.x); fma4(acc[1], w4, xa.y);
            fma4(acc[2], w4, xa.z); fma4(acc[3], w4, xa.w);
            fma4(acc[4], w4, xb.x); fma4(acc[5], w4, xb.y);
            fma4(acc[6], w4, xb.z); fma4(acc[7], w4, xb.w);
        }
    }
#pragma unroll
    for (int j = 0; j < 8; j++) {
        int m = tm * 8 + j;
        *reinterpret_cast<float4*>(&Y[(size_t)(o0 + m) * CS + tc * 4]) = acc[j];
    }
}

__global__ void __launch_bounds__(128) inv1_tiled_kernel(
    const float* __restrict__ X2, float* __restrict__ Y,
    const float* __restrict__ W, const float* __restrict__ mask) {
    constexpr int SPAD = 33;
    __shared__ __align__(16) float xs[96 * SPAD];
    int t = threadIdx.x;
    int o0 = blockIdx.x * 64;
    int oz = o0 >> 12, oy = (o0 >> 6) & 63;
    int m0 = (((oz >> 1) * GH2) + (oy >> 1)) * GW2;
    int tapBase = ((oz & 1) * 2 + (oy & 1)) * 2;

    for (int i = t; i < 32 * 24; i += 128) {
        int s = i / 24, c4 = i - s * 24;
        float4 v = *reinterpret_cast<const float4*>(&X2[(size_t)(m0 + s) * CS + c4 * 4]);
        xs[(c4 * 4 + 0) * SPAD + s] = v.x;
        xs[(c4 * 4 + 1) * SPAD + s] = v.y;
        xs[(c4 * 4 + 2) * SPAD + s] = v.z;
        xs[(c4 * 4 + 3) * SPAD + s] = v.w;
    }
    __syncthreads();

    int tc = t & 15, tm = t >> 4;
    const float* wE = W + (size_t)tapBase * 96 * 64 + tc * 4;
    const float* wO = wE + 96 * 64;
    float4 acc[8];
#pragma unroll
    for (int j = 0; j < 8; j++) acc[j] = make_float4(0.f, 0.f, 0.f, 0.f);
#pragma unroll 4
    for (int ci = 0; ci < 96; ci++) {
        float4 we = *reinterpret_cast<const float4*>(wE + ci * 64);
        float4 wo = *reinterpret_cast<const float4*>(wO + ci * 64);
        float x0 = xs[ci * SPAD + tm * 4 + 0];
        float x1 = xs[ci * SPAD + tm * 4 + 1];
        float x2 = xs[ci * SPAD + tm * 4 + 2];
        float x3 = xs[ci * SPAD + tm * 4 + 3];
        fma4(acc[0], we, x0); fma4(acc[1], wo, x0);
        fma4(acc[2], we, x1); fma4(acc[3], wo, x1);
        fma4(acc[4], we, x2); fma4(acc[5], wo, x2);
        fma4(acc[6], we, x3); fma4(acc[7], wo, x3);
    }
#pragma unroll
    for (int j = 0; j < 8; j++) {
        int o = o0 + tm * 8 + j;
        float mv = mask[o];
        float4 r = acc[j];
        r.x *= mv; r.y *= mv; r.z *= mv; r.w *= mv;
        *reinterpret_cast<float4*>(&Y[(size_t)o * CS + tc * 4]) = r;
    }
}

__global__ void __launch_bounds__(256) inv0_kernel(
    const float* __restrict__ X, float* __restrict__ out,
    const int* __restrict__ coors, const int* __restrict__ order,
    const float* __restrict__ Wt, int n) {
    constexpr int CIN = 64, COUT = 32;
    __shared__ __align__(16) float xs[8][CIN];
    int g = threadIdx.x >> 5, t = threadIdx.x & 31;
    int idx = blockIdx.x * 8 + g;
    if (idx >= n) return;
    int p = order[idx];
    int z = coors[p * 4 + 1], y = coors[p * 4 + 2], x = coors[p * 4 + 3];

    int mzv[2], wzv[2], myv[2], wyv[2], mxv[2], wxv[2];
    int nzc = 0, nyc = 0, nxc = 0;
    if ((z & 1) == 0) { mzv[0] = z >> 1; wzv[0] = 1; nzc = 1; }
    else {
        mzv[nzc] = z >> 1; wzv[nzc] = 2; nzc++;
        if ((z >> 1) + 1 < GD1) { mzv[nzc] = (z >> 1) + 1; wzv[nzc] = 0; nzc++; }
    }
    if ((y & 1) == 0) { myv[0] = y >> 1; wyv[0] = 1; nyc = 1; }
    else {
        myv[nyc] = y >> 1; wyv[nyc] = 2; nyc++;
        if ((y >> 1) + 1 < GH1) { myv[nyc] = (y >> 1) + 1; wyv[nyc] = 0; nyc++; }
    }
    if ((x & 1) == 0) { mxv[0] = x >> 1; wxv[0] = 1; nxc = 1; }
    else {
        mxv[nxc] = x >> 1; wxv[nxc] = 2; nxc++;
        if ((x >> 1) + 1 < GW1) { mxv[nxc] = (x >> 1) + 1; wxv[nxc] = 0; nxc++; }
    }

    float4 acc = make_float4(0.f, 0.f, 0.f, 0.f);
    for (int a = 0; a < nzc; a++)
        for (int b = 0; b < nyc; b++)
            for (int c = 0; c < nxc; c++) {
                int m = ((mzv[a] * GH1) + myv[b]) * GW1 + mxv[c];
                int tap = (wzv[a] * 3 + wyv[b]) * 3 + wxv[c];
                xs[g][t] = X[(size_t)m * CS + t];
                xs[g][t + 32] = X[(size_t)m * CS + t + 32];
                __syncwarp();
                dotrow4<CIN>(Wt + (tap * COUT + t) * CIN, xs[g], acc);
                __syncwarp();
            }
    out[(size_t)p * COUT + t] = acc.x + acc.y + acc.z + acc.w;
}

// ---------------- launch ----------------
extern "C" void kernel_launch(void* const* d_in, const int* in_sizes, int n_in,
                              void* d_out, int out_size) {
    const float* features = (const float*)d_in[0];
    const int* coors      = (const int*)d_in[1];
    int wb = n_in - 10;
    const float* w_sub0  = (const float*)d_in[wb + 0];
    const float* w_sub1  = (const float*)d_in[wb + 1];
    const float* w_sub2  = (const float*)d_in[wb + 2];
    const float* w_sub3  = (const float*)d_in[wb + 3];
    const float* w_down0 = (const float*)d_in[wb + 4];
    const float* w_sub4  = (const float*)d_in[wb + 5];
    const float* w_sub5  = (const float*)d_in[wb + 6];
    const float* w_down1 = (const float*)d_in[wb + 7];
    const float* w_inv1  = (const float*)d_in[wb + 8];
    const float* w_inv0  = (const float*)d_in[wb + 9];

    int n = in_sizes[0] / 3;

    float *fA, *cA, *c2p, *maskp, *pwi0;
    int *v2p, *orderp, *blkCnt, *blkOff;
    __nv_bfloat16 *fX, *fY, *cX, *cY;
    __nv_bfloat16 *b1h, *b1l, *b2h, *b2l, *b3h, *b3l, *bd0h, *bd0l, *b4h, *b4l, *b5h, *b5l;
    cudaGetSymbolAddress((void**)&fA, g_fineA);
    cudaGetSymbolAddress((void**)&cA, g_cA);
    cudaGetSymbolAddress((void**)&c2p, g_c2);
    cudaGetSymbolAddress((void**)&maskp, g_mask);
    cudaGetSymbolAddress((void**)&pwi0, g_wi0);
    cudaGetSymbolAddress((void**)&v2p, g_vox2pt);
    cudaGetSymbolAddress((void**)&orderp, g_order);
    cudaGetSymbolAddress((void**)&blkCnt, g_blkCnt);
    cudaGetSymbolAddress((void**)&blkOff, g_blkOff);
    cudaGetSymbolAddress((void**)&fX, g_fX);
    cudaGetSymbolAddress((void**)&fY, g_fY);
    cudaGetSymbolAddress((void**)&cX, g_cX);
    cudaGetSymbolAddress((void**)&cY, g_cY);
    cudaGetSymbolAddress((void**)&b1h, g_b1h);  cudaGetSymbolAddress((void**)&b1l, g_b1l);
    cudaGetSymbolAddress((void**)&b2h, g_b2h);  cudaGetSymbolAddress((void**)&b2l, g_b2l);
    cudaGetSymbolAddress((void**)&b3h, g_b3h);  cudaGetSymbolAddress((void**)&b3l, g_b3l);
    cudaGetSymbolAddress((void**)&bd0h, g_bd0h); cudaGetSymbolAddress((void**)&bd0l, g_bd0l);
    cudaGetSymbolAddress((void**)&b4h, g_b4h);  cudaGetSymbolAddress((void**)&b4l, g_b4l);
    cudaGetSymbolAddress((void**)&b5h, g_b5h);  cudaGetSymbolAddress((void**)&b5l, g_b5l);

    // smem: 4 A-buffers + 4 B-buffers (double-buffered hi/lo), or out-tile
    constexpr int SM_F3232 = 4 * 256 * 40 * 2 + 4 * 32 * 40 * 2;    // 92160
    constexpr int SM_F3264 = 4 * 256 * 40 * 2 + 4 * 32 * 72 * 2;    // 100352
    constexpr int SM_F6464 = 4 * 128 * 72 * 2 + 4 * 64 * 72 * 2;    // 110592
    constexpr int SM_C64   = 4 * 128 * 72 * 2 + 4 * 64 * 104 * 2;   // 126976
    constexpr int SM_C96   = 4 * 128 * 104 * 2 + 4 * 96 * 104 * 2;  // 186368
    cudaFuncSetAttribute(conv_fine_wmma<32, 32, 256>, cudaFuncAttributeMaxDynamicSharedMemorySize, SM_F3232);
    cudaFuncSetAttribute(conv_fine_wmma<32, 64, 256>, cudaFuncAttributeMaxDynamicSharedMemorySize, SM_F3264);
    cudaFuncSetAttribute(conv_fine_wmma<64, 64, 128>, cudaFuncAttributeMaxDynamicSharedMemorySize, SM_F6464);
    cudaFuncSetAttribute(conv_dense_wmma<64, 64, 1, true>, cudaFuncAttributeMaxDynamicSharedMemorySize, SM_F6464);
    cudaFuncSetAttribute(conv_dense_wmma<64, 96, 0, true>, cudaFuncAttributeMaxDynamicSharedMemorySize, SM_C64);
    cudaFuncSetAttribute(conv_dense_wmma<96, 96, 0, false>, cudaFuncAttributeMaxDynamicSharedMemorySize, SM_C96);

    int nb256 = (n + 255) / 256;
    int nb128 = (n + 127) / 128;

    scatter_kernel<<<(n + 255) / 256, 256>>>(features, coors, fA, v2p, n);                    // 1
    count_kernel<<<NVB, 256>>>(v2p, blkCnt);                                                  // 2
    scan_kernel<<<1, 32>>>(blkCnt, blkOff);                                                   // 3
    compact_kernel<<<NVB, 256>>>(v2p, blkOff, orderp);                                        // 4
    bprep_kernel<<<(27 * 32 * 32 + 255) / 256, 256>>>(w_sub1, b1h, b1l, 27 * 32 * 32);        // 5
    conv_sub0_kernel<<<(n + 7) / 8, 256>>>(fA, fX, coors, orderp, w_sub0, n);                 // 6
    conv_fine_wmma<32, 32, 256><<<nb256, 256, SM_F3232>>>(fX, fY, coors, orderp, b1h, b1l, n);// 7
    bprep_kernel<<<(27 * 32 * 64 + 255) / 256, 256>>>(w_sub2, b2h, b2l, 27 * 32 * 64);        // 8
    conv_fine_wmma<32, 64, 256><<<nb256, 256, SM_F3264>>>(fY, fX, coors, orderp, b2h, b2l, n);// 9
    bprep_kernel<<<(27 * 64 * 64 + 255) / 256, 256>>>(w_sub3, b3h, b3l, 27 * 64 * 64);        // 10
    conv_fine_wmma<64, 64, 128><<<nb128, 256, SM_F6464>>>(fX, fY, coors, orderp, b3h, b3l, n);// 11
    mask_kernel<<<(n + 255) / 256, 256>>>(coors, maskp, n);                                   // 12
    bprep_kernel<<<(27 * 64 * 64 + 255) / 256, 256>>>(w_down0, bd0h, bd0l, 27 * 64 * 64);     // 13
    conv_dense_wmma<64, 64, 1, true><<<NC1 / 128, 256, SM_F6464>>>(fY, nullptr, cX,
                                                                   bd0h, bd0l, nullptr);      // 14
    bprep_kernel<<<(27 * 64 * 96 + 255) / 256, 256>>>(w_sub4, b4h, b4l, 27 * 64 * 96);        // 15
    bprep_kernel<<<(27 * 96 * 96 + 255) / 256, 256>>>(w_sub5, b5h, b5l, 27 * 96 * 96);        // 16
    conv_dense_wmma<64, 96, 0, true><<<NC1 / 128, 256, SM_C64>>>(cX, nullptr, cY,
                                                                 b4h, b4l, maskp);            // 17
    conv_dense_wmma<96, 96, 0, false><<<NC1 / 128, 256, SM_C96>>>(cY, cA, nullptr,
                                                                  b5h, b5l, maskp);           // 18
    conv_down1_kernel<<<NC2 / 64, 192>>>(cA, c2p, w_down1);                                   // 19
    repack_kernel<<<(27 * 64 * 32 + 255) / 256, 256>>>(w_inv0, pwi0, 27, 64, 32);             // 20
    inv1_tiled_kernel<<<NC1 / 64, 128>>>(c2p, cA, w_inv1, maskp);                             // 21
    inv0_kernel<<<(n + 7) / 8, 256>>>(cA, (float*)d_out, coors, orderp, pwi0, n);             // 22
}